// round 13
// baseline (speedup 1.0000x reference)
#include <cuda_runtime.h>
#include <cuda_fp16.h>
#include <math.h>
#include <stdint.h>

#define NN   50000
#define EE   800000
#define FIN  64
#define HID  128
#define HEADS 4
#define HOUT 512
#define LAYERS 3
#define NEG_SLOPE 0.2f
#define SCAN_B 1024
#define NBLK ((NN + SCAN_B - 1) / SCAN_B)

#define IMG_EMB 0
#define IMG_WB  4096
#define IMG_P1  (4096 + 3 * 65536)
#define IMG_P2  (IMG_P1 + 8192)
#define IMG_TOTAL (IMG_P2 + 8192)

// ---------------- scratch ----------------
__device__ float    g_hA[(size_t)NN * HID];
__device__ float    g_hB[(size_t)NN * HID];
__device__ __half   g_hAh[(size_t)NN * HID];
__device__ __half   g_hBh[(size_t)NN * HID];
__device__ __half   g_xh[(size_t)NN * FIN];
__device__ __half   g_xlrh[(size_t)NN * 1024];
__device__ float    g_zf[(size_t)NN * 256];
__device__ uint32_t g_img[IMG_TOTAL];
__device__ float    g_bB[(size_t)LAYERS * 1024];
__device__ float    g_p2b[128];
__device__ int      g_deg[NN];
__device__ int      g_offs[NN + 1];
__device__ int      g_cursor[NN];
__device__ int      g_csr[EE];
__device__ int      g_blksum[NBLK];
__device__ int      g_blkoff[NBLK];

__device__ __forceinline__ void mma_f16(float* d, const uint32_t* a, const uint32_t* b) {
    asm volatile(
        "mma.sync.aligned.m16n8k16.row.col.f32.f16.f16.f32 "
        "{%0,%1,%2,%3}, {%4,%5,%6,%7}, {%8,%9}, {%0,%1,%2,%3};"
        : "+f"(d[0]), "+f"(d[1]), "+f"(d[2]), "+f"(d[3])
        : "r"(a[0]), "r"(a[1]), "r"(a[2]), "r"(a[3]), "r"(b[0]), "r"(b[1]));
}
__device__ __forceinline__ uint32_t smem_u32(const void* p) {
    uint32_t a;
    asm("{ .reg .u64 t; cvta.to.shared.u64 t, %1; cvt.u32.u64 %0, t; }" : "=r"(a) : "l"(p));
    return a;
}

// ---------------- prep: fp16 B fragment images + bias packing ----------------
__global__ void k_img(const float* __restrict__ emb_W, const float* __restrict__ Wl,
                      const float* __restrict__ Wr, const float* __restrict__ p1_W,
                      const float* __restrict__ p2_W,
                      const float* __restrict__ bl, const float* __restrict__ br,
                      const float* __restrict__ p2_b,
                      uint32_t* __restrict__ img, float* __restrict__ bB,
                      float* __restrict__ p2bp) {
    int w = blockIdx.x * blockDim.x + threadIdx.x;
    if (w >= IMG_TOTAL) return;
    if (w < LAYERS * 1024) {
        int l = w / 1024, n = w % 1024;
        bB[w] = (n < HOUT) ? bl[l * HOUT + n] : br[l * HOUT + n - HOUT];
    }
    if (w < 128) p2bp[w] = (w < 64) ? p2_b[w] : 0.f;

    int rem, nc, seg;
    if (w < IMG_WB)      { seg = 0; rem = w;           nc = 2; }
    else if (w < IMG_P1) { seg = 1; rem = w - IMG_WB;  nc = 4; }
    else if (w < IMG_P2) { seg = 2; rem = w - IMG_P1;  nc = 4; }
    else                 { seg = 3; rem = w - IMG_P2;  nc = 4; }
    int layer = 0;
    if (seg == 1) { layer = rem / 65536; rem %= 65536; }
    int cw = nc * 2048;
    int blk = rem / cw;
    int r2 = rem % cw;
    int kc = r2 / 2048;
    int u = r2 % 2048;
    int comp = u & 3;
    int lane = (u >> 2) & 31;
    int g = u >> 7;
    int lig = lane & 3, grp = lane >> 2;
    int k16 = comp >> 1, pairsel = comp & 1;
    int k = kc * 32 + k16 * 16 + pairsel * 8 + lig * 2;
    int n = blk * 128 + g * 8 + grp;
    float lo, hi;
    if (seg == 0) {
        lo = emb_W[k * HID + n];
        hi = emb_W[(k + 1) * HID + n];
    } else if (seg == 1) {
        if (n < HOUT) {
            lo = Wl[((size_t)layer * HID + k) * HOUT + n];
            hi = Wl[((size_t)layer * HID + k + 1) * HOUT + n];
        } else {
            lo = Wr[((size_t)layer * HID + k) * HOUT + (n - HOUT)];
            hi = Wr[((size_t)layer * HID + k + 1) * HOUT + (n - HOUT)];
        }
    } else if (seg == 2) {
        lo = p1_W[k * HID + n];
        hi = p1_W[(k + 1) * HID + n];
    } else {
        lo = (n < 64) ? p2_W[k * 64 + n] : 0.f;
        hi = (n < 64) ? p2_W[(k + 1) * 64 + n] : 0.f;
    }
    __half2 h2 = __floats2half2_rn(lo, hi);
    img[w] = *(uint32_t*)&h2;
}

__global__ void k_h2(const float* __restrict__ x, __half* __restrict__ xh, int n) {
    int i = blockIdx.x * blockDim.x + threadIdx.x;
    if (i < n) xh[i] = __float2half(x[i]);
}

// ---------------- CSR build ----------------
__global__ void k_zero_int(int* p, int n) {
    int i = blockIdx.x * blockDim.x + threadIdx.x;
    if (i < n) p[i] = 0;
}
__global__ void k_count_deg(const int* __restrict__ dst, int* __restrict__ deg, int e) {
    int i = blockIdx.x * blockDim.x + threadIdx.x;
    if (i < e) atomicAdd(&deg[dst[i]], 1);
}
__global__ void k_scan_part(const int* __restrict__ deg, int* __restrict__ offs,
                            int* __restrict__ blksum, int n) {
    __shared__ int wsum[32];
    int gid = blockIdx.x * SCAN_B + threadIdx.x;
    int lane = threadIdx.x & 31, wid = threadIdx.x >> 5;
    int v = (gid < n) ? deg[gid] : 0;
    int s = v;
    #pragma unroll
    for (int o = 1; o < 32; o <<= 1) {
        int t = __shfl_up_sync(0xffffffffu, s, o);
        if (lane >= o) s += t;
    }
    if (lane == 31) wsum[wid] = s;
    __syncthreads();
    if (wid == 0) {
        int ws = wsum[lane];
        #pragma unroll
        for (int o = 1; o < 32; o <<= 1) {
            int t = __shfl_up_sync(0xffffffffu, ws, o);
            if (lane >= o) ws += t;
        }
        wsum[lane] = ws;
    }
    __syncthreads();
    int base = wid ? wsum[wid - 1] : 0;
    int incl = base + s;
    if (gid < n) offs[gid] = incl - v;
    if (threadIdx.x == SCAN_B - 1) blksum[blockIdx.x] = incl;
}
__global__ void k_scan_blk(const int* __restrict__ blksum, int* __restrict__ blkoff,
                           int* __restrict__ offs, int nblk, int n) {
    __shared__ int sm[64];
    int t = threadIdx.x;
    int v = (t < nblk) ? blksum[t] : 0;
    sm[t] = v;
    __syncthreads();
    #pragma unroll
    for (int d = 1; d < 64; d <<= 1) {
        int tv = (t >= d) ? sm[t - d] : 0;
        __syncthreads();
        sm[t] += tv;
        __syncthreads();
    }
    if (t < nblk) blkoff[t] = sm[t] - v;
    if (t == 63) offs[n] = sm[63];
}
__global__ void k_scan_add(int* __restrict__ offs, const int* __restrict__ blkoff,
                           int* __restrict__ cursor, int n) {
    int gid = blockIdx.x * SCAN_B + threadIdx.x;
    if (gid < n) {
        int o = offs[gid] + blkoff[blockIdx.x];
        offs[gid] = o;
        cursor[gid] = o;
    }
}
__global__ void k_fill_csr(const int* __restrict__ src, const int* __restrict__ dst,
                           int* __restrict__ cursor, int* __restrict__ csr, int e) {
    int i = blockIdx.x * blockDim.x + threadIdx.x;
    if (i < e) {
        int p = atomicAdd(&cursor[dst[i]], 1);
        csr[p] = src[i];
    }
}

// ---------------- GEMM v5 (R10 exact): fp16 mma, full-K cp.async pipeline ----------------
#define STAGE_B 18432
#define G5_SMEM (4 * STAGE_B)
#define CPWAIT(n) asm volatile("cp.async.wait_group " #n ";")

template <int KT, int MODE>
__global__ __launch_bounds__(128, 2) void k_gemm5(
    const __half* __restrict__ A, const uint32_t* __restrict__ img,
    const float* __restrict__ bias, float* __restrict__ C, __half* __restrict__ Ch,
    int M, int Ns, int relu) {
    extern __shared__ uint32_t sm[];
    constexpr int NK = KT / 32;
    int tid = threadIdx.x;
    int wid = tid >> 5, lane = tid & 31;
    int grp = lane >> 2, lig = lane & 3;
    const int wm = (wid & 1) * 64;
    const int wg8 = (wid >> 1) * 8;
    const int bm = blockIdx.x * 128, bn = blockIdx.y * 128;
    const uint32_t* imgB = img + (size_t)blockIdx.y * NK * 2048;
    uint32_t sbase = smem_u32(sm);

    float acc[4][8][4];
    #pragma unroll
    for (int i = 0; i < 4; i++)
        #pragma unroll
        for (int j = 0; j < 8; j++)
            #pragma unroll
            for (int q = 0; q < 4; q++) acc[i][j][q] = 0.f;

    auto stage = [&](int kc) {
        uint32_t abase = sbase + kc * STAGE_B;
        #pragma unroll
        for (int i = 0; i < 8; i++) {
            int idx = tid + i * 128;
            int r = idx >> 3, s = idx & 7;
            int gr = bm + r;
            uint32_t dst = abase + (uint32_t)(r * 80 + s * 8);
            const __half* src = A + (size_t)gr * KT + kc * 32 + s * 4;
            int sz = (gr < M) ? 8 : 0;
            asm volatile("cp.async.ca.shared.global [%0], [%1], 8, %2;"
                         :: "r"(dst), "l"(src), "r"(sz));
        }
        uint32_t bbase = abase + 2560 * 4;
        const uint32_t* bsrc = imgB + kc * 2048;
        #pragma unroll
        for (int i = 0; i < 4; i++) {
            int idx = tid + i * 128;
            uint32_t dst = bbase + (uint32_t)idx * 16;
            asm volatile("cp.async.ca.shared.global [%0], [%1], 16, 16;"
                         :: "r"(dst), "l"(bsrc + idx * 4));
        }
        asm volatile("cp.async.commit_group;");
    };

    #pragma unroll
    for (int kc = 0; kc < NK; kc++) stage(kc);

    auto compute = [&](int kc) {
        const uint32_t* As = sm + kc * 4608;
        const uint32_t* Bs = As + 2560;
        uint4 bq[8];
        #pragma unroll
        for (int nt = 0; nt < 8; nt++)
            bq[nt] = *(const uint4*)(Bs + ((wg8 + nt) * 32 + lane) * 4);
        #pragma unroll
        for (int k16 = 0; k16 < 2; k16++) {
            #pragma unroll
            for (int mt = 0; mt < 4; mt++) {
                int rw = (wm + mt * 16 + grp) * 20 + k16 * 8 + lig;
                uint32_t av[4];
                av[0] = As[rw];
                av[1] = As[rw + 160];
                av[2] = As[rw + 4];
                av[3] = As[rw + 164];
                #pragma unroll
                for (int nt = 0; nt < 8; nt++) {
                    uint32_t bv[2];
                    if (k16 == 0) { bv[0] = bq[nt].x; bv[1] = bq[nt].y; }
                    else          { bv[0] = bq[nt].z; bv[1] = bq[nt].w; }
                    mma_f16(acc[mt][nt], av, bv);
                }
            }
        }
    };

    if (NK == 4) {
        CPWAIT(3); __syncthreads(); compute(0);
        CPWAIT(2); __syncthreads(); compute(1);
        CPWAIT(1); __syncthreads(); compute(2);
        CPWAIT(0); __syncthreads(); compute(3);
    } else {
        CPWAIT(1); __syncthreads(); compute(0);
        CPWAIT(0); __syncthreads(); compute(1);
    }

    // epilogue (R10 exact: mt outer)
    #pragma unroll
    for (int mt = 0; mt < 4; mt++) {
        #pragma unroll
        for (int nt = 0; nt < 8; nt++) {
            int col = bn + (wg8 + nt) * 8 + lig * 2;
            float b0 = __ldg(bias + col), b1 = __ldg(bias + col + 1);
            int row0 = bm + wm + mt * 16 + grp;
            int row1 = row0 + 8;
            float v0 = acc[mt][nt][0] + b0;
            float v1 = acc[mt][nt][1] + b1;
            float v2 = acc[mt][nt][2] + b0;
            float v3 = acc[mt][nt][3] + b1;
            if (relu) {
                v0 = fmaxf(v0, 0.f); v1 = fmaxf(v1, 0.f);
                v2 = fmaxf(v2, 0.f); v3 = fmaxf(v3, 0.f);
            }
            if (MODE == 0) {
                if (row0 < M) {
                    *(float2*)(C + (size_t)row0 * Ns + col) = make_float2(v0, v1);
                    if (Ch) *(__half2*)(Ch + (size_t)row0 * Ns + col) = __floats2half2_rn(v0, v1);
                }
                if (row1 < M) {
                    *(float2*)(C + (size_t)row1 * Ns + col) = make_float2(v2, v3);
                    if (Ch) *(__half2*)(Ch + (size_t)row1 * Ns + col) = __floats2half2_rn(v2, v3);
                }
            } else {
                if (row0 < M) *(__half2*)(Ch + (size_t)row0 * 1024 + col) = __floats2half2_rn(v0, v1);
                if (row1 < M) *(__half2*)(Ch + (size_t)row1 * 1024 + col) = __floats2half2_rn(v2, v3);
            }
        }
    }
}

// ---------------- GATv2 edge kernel: 2 warps per (node,head), online softmax + merge ----------------
__device__ __forceinline__ float h2dot(const __half2 a01, const __half2 a23,
                                       const __half2 xr01, const __half2 xr23,
                                       const __half2 neg2,
                                       const uint2 raw, float2* f01, float2* f23) {
    __half2 v01 = *(const __half2*)&raw.x, v23 = *(const __half2*)&raw.y;
    __half2 m01 = __hadd2(v01, xr01), m23 = __hadd2(v23, xr23);
    m01 = __hmax2(m01, __hmul2(m01, neg2));
    m23 = __hmax2(m23, __hmul2(m23, neg2));
    __half2 d2 = __hfma2(a23, m23, __hmul2(a01, m01));
    float2 df = __half22float2(d2);
    *f01 = __half22float2(v01);
    *f23 = __half22float2(v23);
    return df.x + df.y;
}

__global__ __launch_bounds__(256) void k_gat_edge(
    const __half* __restrict__ xlr, const float* __restrict__ att,
    const float* __restrict__ cbias,
    const float* __restrict__ hin, float* __restrict__ hout, __half* __restrict__ houth,
    const int* __restrict__ offs, const int* __restrict__ csr) {
    int node = blockIdx.x;
    int wid = threadIdx.x >> 5;
    int w = wid & 3;            // head
    int hf = wid >> 2;          // half 0/1
    int lane = threadIdx.x & 31;
    __shared__ float sacc[2][HEADS][HID];
    __shared__ float sstat[2][HEADS][2];   // emax, denom

    int beg = offs[node], end = offs[node + 1];
    int mid = beg + ((end - beg) >> 1);
    int lo = hf ? mid : beg;
    int hi = hf ? end : mid;

    const int off = w * HID + lane * 4;
    uint2 xrraw = *(const uint2*)(xlr + (size_t)node * 1024 + HOUT + off);
    const __half2 xr01 = *(const __half2*)&xrraw.x, xr23 = *(const __half2*)&xrraw.y;
    float4 a4 = *(const float4*)(att + w * HID + lane * 4);
    const __half2 a01 = __floats2half2_rn(a4.x, a4.y);
    const __half2 a23 = __floats2half2_rn(a4.z, a4.w);
    const __half2 neg2 = __float2half2_rn(NEG_SLOPE);

    float emax = -1e30f, denom = 0.f;
    float4 acc = make_float4(0.f, 0.f, 0.f, 0.f);
    int i = lo;
    for (; i + 3 < hi; i += 4) {
        int s0 = __ldg(csr + i),     s1 = __ldg(csr + i + 1);
        int s2 = __ldg(csr + i + 2), s3 = __ldg(csr + i + 3);
        uint2 r0 = *(const uint2*)(xlr + (size_t)s0 * 1024 + off);
        uint2 r1 = *(const uint2*)(xlr + (size_t)s1 * 1024 + off);
        uint2 r2 = *(const uint2*)(xlr + (size_t)s2 * 1024 + off);
        uint2 r3 = *(const uint2*)(xlr + (size_t)s3 * 1024 + off);
        float2 v0a, v0b, v1a, v1b, v2a, v2b, v3a, v3b;
        float p0 = h2dot(a01, a23, xr01, xr23, neg2, r0, &v0a, &v0b);
        float p1 = h2dot(a01, a23, xr01, xr23, neg2, r1, &v1a, &v1b);
        float p2 = h2dot(a01, a23, xr01, xr23, neg2, r2, &v2a, &v2b);
        float p3 = h2dot(a01, a23, xr01, xr23, neg2, r3, &v3a, &v3b);
        #pragma unroll
        for (int o = 16; o; o >>= 1) {
            p0 += __shfl_xor_sync(0xffffffffu, p0, o);
            p1 += __shfl_xor_sync(0xffffffffu, p1, o);
            p2 += __shfl_xor_sync(0xffffffffu, p2, o);
            p3 += __shfl_xor_sync(0xffffffffu, p3, o);
        }
        float nm = fmaxf(fmaxf(emax, fmaxf(p0, p1)), fmaxf(p2, p3));
        float sc = __expf(emax - nm);
        denom *= sc;
        acc.x *= sc; acc.y *= sc; acc.z *= sc; acc.w *= sc;
        emax = nm;
        float w0 = __expf(p0 - nm), w1 = __expf(p1 - nm);
        float w2 = __expf(p2 - nm), w3 = __expf(p3 - nm);
        denom += (w0 + w1) + (w2 + w3);
        acc.x += w0 * v0a.x + w1 * v1a.x + w2 * v2a.x + w3 * v3a.x;
        acc.y += w0 * v0a.y + w1 * v1a.y + w2 * v2a.y + w3 * v3a.y;
        acc.z += w0 * v0b.x + w1 * v1b.x + w2 * v2b.x + w3 * v3b.x;
        acc.w += w0 * v0b.y + w1 * v1b.y + w2 * v2b.y + w3 * v3b.y;
    }
    for (; i < hi; i++) {
        int s0 = __ldg(csr + i);
        uint2 r0 = *(const uint2*)(xlr + (size_t)s0 * 1024 + off);
        float2 v0a, v0b;
        float p0 = h2dot(a01, a23, xr01, xr23, neg2, r0, &v0a, &v0b);
        #pragma unroll
        for (int o = 16; o; o >>= 1) p0 += __shfl_xor_sync(0xffffffffu, p0, o);
        float nm = fmaxf(emax, p0);
        float sc = __expf(emax - nm);
        denom *= sc;
        acc.x *= sc; acc.y *= sc; acc.z *= sc; acc.w *= sc;
        emax = nm;
        float w0 = __expf(p0 - nm);
        denom += w0;
        acc.x += w0 * v0a.x; acc.y += w0 * v0a.y;
        acc.z += w0 * v0b.x; acc.w += w0 * v0b.y;
    }
    sacc[hf][w][lane * 4 + 0] = acc.x;
    sacc[hf][w][lane * 4 + 1] = acc.y;
    sacc[hf][w][lane * 4 + 2] = acc.z;
    sacc[hf][w][lane * 4 + 3] = acc.w;
    if (lane == 0) { sstat[hf][w][0] = emax; sstat[hf][w][1] = denom; }
    __syncthreads();

    // merge halves (warps 0..3)
    if (hf == 0) {
        float e0 = sstat[0][w][0], d0 = sstat[0][w][1];
        float e1 = sstat[1][w][0], d1 = sstat[1][w][1];
        float m = fmaxf(e0, e1);
        float s0 = __expf(e0 - m), s1 = __expf(e1 - m);
        float d = d0 * s0 + d1 * s1;
        float inv = d > 0.f ? 1.f / d : 0.f;
        #pragma unroll
        for (int j = 0; j < 4; j++) {
            int idx = lane * 4 + j;
            float a = sacc[0][w][idx] * s0 + sacc[1][w][idx] * s1;
            sacc[0][w][idx] = a * inv;
        }
    }
    __syncthreads();

    if (threadIdx.x < HID) {
        int t = threadIdx.x;
        float sv = (sacc[0][0][t] + sacc[0][1][t] + sacc[0][2][t] + sacc[0][3][t]) * 0.25f
                 + cbias[t] + hin[(size_t)node * HID + t];
        sv = fmaxf(sv, 0.f);
        hout[(size_t)node * HID + t] = sv;
        houth[(size_t)node * HID + t] = __float2half(sv);
    }
}

// ---------------- final predictor head ----------------
__global__ void k_pred3(const float* __restrict__ z2, const float* __restrict__ W,
                        const float* __restrict__ b, float* __restrict__ out, int n) {
    int warp = (blockIdx.x * blockDim.x + threadIdx.x) >> 5;
    int lane = threadIdx.x & 31;
    if (warp >= n) return;
    const float* zr = z2 + (size_t)warp * 128;
    float p = zr[lane] * W[lane] + zr[lane + 32] * W[lane + 32];
    #pragma unroll
    for (int o = 16; o; o >>= 1) p += __shfl_xor_sync(0xffffffffu, p, o);
    if (lane == 0) {
        float s = p + b[0];
        s = fminf(fmaxf(s, -15.f), 15.f);
        out[warp] = s;
    }
}

// ---------------- launch ----------------
extern "C" void kernel_launch(void* const* d_in, const int* in_sizes, int n_in,
                              void* d_out, int out_size) {
    const float* x      = (const float*)d_in[0];
    const int*   eidx   = (const int*)d_in[1];
    const float* emb_W  = (const float*)d_in[3];
    const float* emb_b  = (const float*)d_in[4];
    const float* Wl     = (const float*)d_in[5];
    const float* bl     = (const float*)d_in[6];
    const float* Wr     = (const float*)d_in[7];
    const float* br     = (const float*)d_in[8];
    const float* att    = (const float*)d_in[9];
    const float* cbias  = (const float*)d_in[10];
    const float* p1_W   = (const float*)d_in[11];
    const float* p1_b   = (const float*)d_in[12];
    const float* p2_W   = (const float*)d_in[13];
    const float* p2_b   = (const float*)d_in[14];
    const float* p3_W   = (const float*)d_in[15];
    const float* p3_b   = (const float*)d_in[16];
    float* out = (float*)d_out;

    const int* srcp = eidx;
    const int* dstp = eidx + EE;

    float *hA, *hB, *zf, *bB, *p2b;
    __half *hAh, *hBh, *xh, *xlrh;
    uint32_t* img;
    int *deg, *offs, *cursor, *csr, *blksum, *blkoff;
    cudaGetSymbolAddress((void**)&hA, g_hA);
    cudaGetSymbolAddress((void**)&hB, g_hB);
    cudaGetSymbolAddress((void**)&hAh, g_hAh);
    cudaGetSymbolAddress((void**)&hBh, g_hBh);
    cudaGetSymbolAddress((void**)&xh, g_xh);
    cudaGetSymbolAddress((void**)&xlrh, g_xlrh);
    cudaGetSymbolAddress((void**)&zf, g_zf);
    cudaGetSymbolAddress((void**)&img, g_img);
    cudaGetSymbolAddress((void**)&bB, g_bB);
    cudaGetSymbolAddress((void**)&p2b, g_p2b);
    cudaGetSymbolAddress((void**)&deg, g_deg);
    cudaGetSymbolAddress((void**)&offs, g_offs);
    cudaGetSymbolAddress((void**)&cursor, g_cursor);
    cudaGetSymbolAddress((void**)&csr, g_csr);
    cudaGetSymbolAddress((void**)&blksum, g_blksum);
    cudaGetSymbolAddress((void**)&blkoff, g_blkoff);

    cudaFuncSetAttribute(k_gemm5<64, 0>,  cudaFuncAttributeMaxDynamicSharedMemorySize, G5_SMEM);
    cudaFuncSetAttribute(k_gemm5<128, 0>, cudaFuncAttributeMaxDynamicSharedMemorySize, G5_SMEM);
    cudaFuncSetAttribute(k_gemm5<128, 1>, cudaFuncAttributeMaxDynamicSharedMemorySize, G5_SMEM);

    const int MB = (NN + 127) / 128;  // 391

    // (1) fp16 fragment images + bias packing
    k_img<<<(IMG_TOTAL + 255) / 256, 256>>>(emb_W, Wl, Wr, p1_W, p2_W, bl, br, p2_b,
                                            img, bB, p2b);
    // (2) x -> fp16
    k_h2<<<(NN * FIN + 255) / 256, 256>>>(x, xh, NN * FIN);
    // (3) embedding
    k_gemm5<64, 0><<<dim3(MB, 1), 128, 2 * STAGE_B>>>(xh, img + IMG_EMB, emb_b, hA, hAh, NN, HID, 1);
    // (4) layer-1 split GEMM  <-- profiled slot
    k_gemm5<128, 1><<<dim3(MB, 8), 128, 4 * STAGE_B>>>(hAh, img + IMG_WB, bB, nullptr, xlrh, NN, 1024, 0);
    // CSR build
    k_zero_int<<<(NN + 255) / 256, 256>>>(deg, NN);
    k_count_deg<<<(EE + 255) / 256, 256>>>(dstp, deg, EE);
    k_scan_part<<<NBLK, SCAN_B>>>(deg, offs, blksum, NN);
    k_scan_blk<<<1, 64>>>(blksum, blkoff, offs, NBLK, NN);
    k_scan_add<<<NBLK, SCAN_B>>>(offs, blkoff, cursor, NN);
    k_fill_csr<<<(EE + 255) / 256, 256>>>(srcp, dstp, cursor, csr, EE);

    // layer 1 edge
    float* hc = hA;   __half* hch = hAh;
    float* hn = hB;   __half* hnh = hBh;
    k_gat_edge<<<NN, 256>>>(xlrh, att, cbias, hc, hn, hnh, offs, csr);
    { float* t = hc; hc = hn; hn = t; __half* th = hch; hch = hnh; hnh = th; }

    // layers 2..3
    for (int l = 1; l < LAYERS; l++) {
        k_gemm5<128, 1><<<dim3(MB, 8), 128, 4 * STAGE_B>>>(
            hch, img + IMG_WB + (size_t)l * 65536, bB + (size_t)l * 1024, nullptr, xlrh, NN, 1024, 0);
        k_gat_edge<<<NN, 256>>>(xlrh, att + (size_t)l * HEADS * HID,
                                cbias + l * HID, hc, hn, hnh, offs, csr);
        float* t = hc; hc = hn; hn = t; __half* th = hch; hch = hnh; hnh = th;
    }

    // predictor MLP
    float* z1f = zf;
    __half* z1h = xlrh;
    float* z2 = zf + (size_t)NN * HID;
    k_gemm5<128, 0><<<dim3(MB, 1), 128, 4 * STAGE_B>>>(hch, img + IMG_P1, p1_b, z1f, z1h, NN, HID, 1);
    k_gemm5<128, 0><<<dim3(MB, 1), 128, 4 * STAGE_B>>>(z1h, img + IMG_P2, p2b, z2, nullptr, NN, HID, 1);
    k_pred3<<<(NN * 32 + 255) / 256, 256>>>(z2, p3_W, p3_b, out, NN);
}

// round 14
// speedup vs baseline: 1.1924x; 1.1924x over previous
#include <cuda_runtime.h>
#include <cuda_fp16.h>
#include <math.h>
#include <stdint.h>

#define NN   50000
#define EE   800000
#define FIN  64
#define HID  128
#define HEADS 4
#define HOUT 512
#define LAYERS 3
#define NEG_SLOPE 0.2f
#define SCAN_B 1024
#define NBLK ((NN + SCAN_B - 1) / SCAN_B)

#define IMG_EMB 0
#define IMG_WB  4096
#define IMG_P1  (4096 + 3 * 65536)
#define IMG_P2  (IMG_P1 + 8192)
#define IMG_TOTAL (IMG_P2 + 8192)

// ---------------- scratch ----------------
__device__ float    g_hA[(size_t)NN * HID];
__device__ float    g_hB[(size_t)NN * HID];
__device__ __half   g_hAh[(size_t)NN * HID];
__device__ __half   g_hBh[(size_t)NN * HID];
__device__ __half   g_xh[(size_t)NN * FIN];
__device__ __half   g_xlrh[(size_t)NN * 1024];
__device__ float    g_zf[(size_t)NN * 256];
__device__ uint32_t g_img[IMG_TOTAL];
__device__ float    g_bB[(size_t)LAYERS * 1024];
__device__ float    g_p2b[128];
__device__ int      g_deg[NN];
__device__ int      g_offs[NN + 1];
__device__ int      g_cursor[NN];
__device__ int      g_csr[EE];
__device__ int      g_blksum[NBLK];
__device__ int      g_blkoff[NBLK];

__device__ __forceinline__ void mma_f16(float* d, const uint32_t* a, const uint32_t* b) {
    asm volatile(
        "mma.sync.aligned.m16n8k16.row.col.f32.f16.f16.f32 "
        "{%0,%1,%2,%3}, {%4,%5,%6,%7}, {%8,%9}, {%0,%1,%2,%3};"
        : "+f"(d[0]), "+f"(d[1]), "+f"(d[2]), "+f"(d[3])
        : "r"(a[0]), "r"(a[1]), "r"(a[2]), "r"(a[3]), "r"(b[0]), "r"(b[1]));
}
__device__ __forceinline__ uint32_t smem_u32(const void* p) {
    uint32_t a;
    asm("{ .reg .u64 t; cvta.to.shared.u64 t, %1; cvt.u32.u64 %0, t; }" : "=r"(a) : "l"(p));
    return a;
}

// ---------------- prep: fp16 B fragment images + bias packing ----------------
__global__ void k_img(const float* __restrict__ emb_W, const float* __restrict__ Wl,
                      const float* __restrict__ Wr, const float* __restrict__ p1_W,
                      const float* __restrict__ p2_W,
                      const float* __restrict__ bl, const float* __restrict__ br,
                      const float* __restrict__ p2_b,
                      uint32_t* __restrict__ img, float* __restrict__ bB,
                      float* __restrict__ p2bp) {
    int w = blockIdx.x * blockDim.x + threadIdx.x;
    if (w >= IMG_TOTAL) return;
    if (w < LAYERS * 1024) {
        int l = w / 1024, n = w % 1024;
        bB[w] = (n < HOUT) ? bl[l * HOUT + n] : br[l * HOUT + n - HOUT];
    }
    if (w < 128) p2bp[w] = (w < 64) ? p2_b[w] : 0.f;

    int rem, nc, seg;
    if (w < IMG_WB)      { seg = 0; rem = w;           nc = 2; }
    else if (w < IMG_P1) { seg = 1; rem = w - IMG_WB;  nc = 4; }
    else if (w < IMG_P2) { seg = 2; rem = w - IMG_P1;  nc = 4; }
    else                 { seg = 3; rem = w - IMG_P2;  nc = 4; }
    int layer = 0;
    if (seg == 1) { layer = rem / 65536; rem %= 65536; }
    int cw = nc * 2048;
    int blk = rem / cw;
    int r2 = rem % cw;
    int kc = r2 / 2048;
    int u = r2 % 2048;
    int comp = u & 3;
    int lane = (u >> 2) & 31;
    int g = u >> 7;
    int lig = lane & 3, grp = lane >> 2;
    int k16 = comp >> 1, pairsel = comp & 1;
    int k = kc * 32 + k16 * 16 + pairsel * 8 + lig * 2;
    int n = blk * 128 + g * 8 + grp;
    float lo, hi;
    if (seg == 0) {
        lo = emb_W[k * HID + n];
        hi = emb_W[(k + 1) * HID + n];
    } else if (seg == 1) {
        if (n < HOUT) {
            lo = Wl[((size_t)layer * HID + k) * HOUT + n];
            hi = Wl[((size_t)layer * HID + k + 1) * HOUT + n];
        } else {
            lo = Wr[((size_t)layer * HID + k) * HOUT + (n - HOUT)];
            hi = Wr[((size_t)layer * HID + k + 1) * HOUT + (n - HOUT)];
        }
    } else if (seg == 2) {
        lo = p1_W[k * HID + n];
        hi = p1_W[(k + 1) * HID + n];
    } else {
        lo = (n < 64) ? p2_W[k * 64 + n] : 0.f;
        hi = (n < 64) ? p2_W[(k + 1) * 64 + n] : 0.f;
    }
    __half2 h2 = __floats2half2_rn(lo, hi);
    img[w] = *(uint32_t*)&h2;
}

__global__ void k_h2(const float* __restrict__ x, __half* __restrict__ xh, int n) {
    int i = blockIdx.x * blockDim.x + threadIdx.x;
    if (i < n) xh[i] = __float2half(x[i]);
}

// ---------------- CSR build ----------------
__global__ void k_zero_int(int* p, int n) {
    int i = blockIdx.x * blockDim.x + threadIdx.x;
    if (i < n) p[i] = 0;
}
__global__ void k_count_deg(const int* __restrict__ dst, int* __restrict__ deg, int e) {
    int i = blockIdx.x * blockDim.x + threadIdx.x;
    if (i < e) atomicAdd(&deg[dst[i]], 1);
}
__global__ void k_scan_part(const int* __restrict__ deg, int* __restrict__ offs,
                            int* __restrict__ blksum, int n) {
    __shared__ int wsum[32];
    int gid = blockIdx.x * SCAN_B + threadIdx.x;
    int lane = threadIdx.x & 31, wid = threadIdx.x >> 5;
    int v = (gid < n) ? deg[gid] : 0;
    int s = v;
    #pragma unroll
    for (int o = 1; o < 32; o <<= 1) {
        int t = __shfl_up_sync(0xffffffffu, s, o);
        if (lane >= o) s += t;
    }
    if (lane == 31) wsum[wid] = s;
    __syncthreads();
    if (wid == 0) {
        int ws = wsum[lane];
        #pragma unroll
        for (int o = 1; o < 32; o <<= 1) {
            int t = __shfl_up_sync(0xffffffffu, ws, o);
            if (lane >= o) ws += t;
        }
        wsum[lane] = ws;
    }
    __syncthreads();
    int base = wid ? wsum[wid - 1] : 0;
    int incl = base + s;
    if (gid < n) offs[gid] = incl - v;
    if (threadIdx.x == SCAN_B - 1) blksum[blockIdx.x] = incl;
}
__global__ void k_scan_blk(const int* __restrict__ blksum, int* __restrict__ blkoff,
                           int* __restrict__ offs, int nblk, int n) {
    __shared__ int sm[64];
    int t = threadIdx.x;
    int v = (t < nblk) ? blksum[t] : 0;
    sm[t] = v;
    __syncthreads();
    #pragma unroll
    for (int d = 1; d < 64; d <<= 1) {
        int tv = (t >= d) ? sm[t - d] : 0;
        __syncthreads();
        sm[t] += tv;
        __syncthreads();
    }
    if (t < nblk) blkoff[t] = sm[t] - v;
    if (t == 63) offs[n] = sm[63];
}
__global__ void k_scan_add(int* __restrict__ offs, const int* __restrict__ blkoff,
                           int* __restrict__ cursor, int n) {
    int gid = blockIdx.x * SCAN_B + threadIdx.x;
    if (gid < n) {
        int o = offs[gid] + blkoff[blockIdx.x];
        offs[gid] = o;
        cursor[gid] = o;
    }
}
__global__ void k_fill_csr(const int* __restrict__ src, const int* __restrict__ dst,
                           int* __restrict__ cursor, int* __restrict__ csr, int e) {
    int i = blockIdx.x * blockDim.x + threadIdx.x;
    if (i < e) {
        int p = atomicAdd(&cursor[dst[i]], 1);
        csr[p] = src[i];
    }
}

// ---------------- GEMM v6: 8 warps of 64x32, v5 full-K cp.async pipeline, B image ----------------
#define STAGE_B 18432
#define G5_SMEM (4 * STAGE_B)
#define CPWAIT(n) asm volatile("cp.async.wait_group " #n ";")

template <int KT, int MODE>
__global__ __launch_bounds__(256, 2) void k_gemm6(
    const __half* __restrict__ A, const uint32_t* __restrict__ img,
    const float* __restrict__ bias, float* __restrict__ C, __half* __restrict__ Ch,
    int M, int Ns, int relu) {
    extern __shared__ uint32_t sm[];
    constexpr int NK = KT / 32;
    int tid = threadIdx.x;
    int wid = tid >> 5, lane = tid & 31;
    int grp = lane >> 2, lig = lane & 3;
    const int wm = (wid & 1) * 64;          // warp row base
    const int wg4 = (wid >> 1) * 4;         // warp col base in g-units (8 cols each)
    const int bm = blockIdx.x * 128, bn = blockIdx.y * 128;
    const uint32_t* imgB = img + (size_t)blockIdx.y * NK * 2048;
    uint32_t sbase = smem_u32(sm);

    float acc[4][4][4];
    #pragma unroll
    for (int i = 0; i < 4; i++)
        #pragma unroll
        for (int j = 0; j < 4; j++)
            #pragma unroll
            for (int q = 0; q < 4; q++) acc[i][j][q] = 0.f;

    auto stage = [&](int kc) {
        uint32_t abase = sbase + kc * STAGE_B;
        // A: 128 rows x 32 halves; 8B copies, 4 per thread
        #pragma unroll
        for (int i = 0; i < 4; i++) {
            int idx = tid + i * 256;
            int r = idx >> 3, s = idx & 7;
            int gr = bm + r;
            uint32_t dst = abase + (uint32_t)(r * 80 + s * 8);
            const __half* src = A + (size_t)gr * KT + kc * 32 + s * 4;
            int sz = (gr < M) ? 8 : 0;
            asm volatile("cp.async.ca.shared.global [%0], [%1], 8, %2;"
                         :: "r"(dst), "l"(src), "r"(sz));
        }
        // B: 2048 words; 16B copies, 2 per thread
        uint32_t bbase = abase + 2560 * 4;
        const uint32_t* bsrc = imgB + kc * 2048;
        #pragma unroll
        for (int i = 0; i < 2; i++) {
            int idx = tid + i * 256;
            uint32_t dst = bbase + (uint32_t)idx * 16;
            asm volatile("cp.async.ca.shared.global [%0], [%1], 16, 16;"
                         :: "r"(dst), "l"(bsrc + idx * 4));
        }
        asm volatile("cp.async.commit_group;");
    };

    #pragma unroll
    for (int kc = 0; kc < NK; kc++) stage(kc);

    auto compute = [&](int kc) {
        const uint32_t* As = sm + kc * 4608;
        const uint32_t* Bs = As + 2560;
        uint4 bq[4];
        #pragma unroll
        for (int nt = 0; nt < 4; nt++)
            bq[nt] = *(const uint4*)(Bs + ((wg4 + nt) * 32 + lane) * 4);
        #pragma unroll
        for (int k16 = 0; k16 < 2; k16++) {
            #pragma unroll
            for (int mt = 0; mt < 4; mt++) {
                int rw = (wm + mt * 16 + grp) * 20 + k16 * 8 + lig;
                uint32_t av[4];
                av[0] = As[rw];
                av[1] = As[rw + 160];
                av[2] = As[rw + 4];
                av[3] = As[rw + 164];
                #pragma unroll
                for (int nt = 0; nt < 4; nt++) {
                    uint32_t bv[2];
                    if (k16 == 0) { bv[0] = bq[nt].x; bv[1] = bq[nt].y; }
                    else          { bv[0] = bq[nt].z; bv[1] = bq[nt].w; }
                    mma_f16(acc[mt][nt], av, bv);
                }
            }
        }
    };

    if (NK == 4) {
        CPWAIT(3); __syncthreads(); compute(0);
        CPWAIT(2); __syncthreads(); compute(1);
        CPWAIT(1); __syncthreads(); compute(2);
        CPWAIT(0); __syncthreads(); compute(3);
    } else {
        CPWAIT(1); __syncthreads(); compute(0);
        CPWAIT(0); __syncthreads(); compute(1);
    }

    // epilogue (mt outer, R10 style)
    #pragma unroll
    for (int mt = 0; mt < 4; mt++) {
        #pragma unroll
        for (int nt = 0; nt < 4; nt++) {
            int col = bn + (wg4 + nt) * 8 + lig * 2;
            float b0 = __ldg(bias + col), b1 = __ldg(bias + col + 1);
            int row0 = bm + wm + mt * 16 + grp;
            int row1 = row0 + 8;
            float v0 = acc[mt][nt][0] + b0;
            float v1 = acc[mt][nt][1] + b1;
            float v2 = acc[mt][nt][2] + b0;
            float v3 = acc[mt][nt][3] + b1;
            if (relu) {
                v0 = fmaxf(v0, 0.f); v1 = fmaxf(v1, 0.f);
                v2 = fmaxf(v2, 0.f); v3 = fmaxf(v3, 0.f);
            }
            if (MODE == 0) {
                if (row0 < M) {
                    *(float2*)(C + (size_t)row0 * Ns + col) = make_float2(v0, v1);
                    if (Ch) *(__half2*)(Ch + (size_t)row0 * Ns + col) = __floats2half2_rn(v0, v1);
                }
                if (row1 < M) {
                    *(float2*)(C + (size_t)row1 * Ns + col) = make_float2(v2, v3);
                    if (Ch) *(__half2*)(Ch + (size_t)row1 * Ns + col) = __floats2half2_rn(v2, v3);
                }
            } else {
                if (row0 < M) *(__half2*)(Ch + (size_t)row0 * 1024 + col) = __floats2half2_rn(v0, v1);
                if (row1 < M) *(__half2*)(Ch + (size_t)row1 * 1024 + col) = __floats2half2_rn(v2, v3);
            }
        }
    }
}

// ---------------- GATv2 edge kernel (R10 exact): fp16 xl|xr, 4-way online softmax ----------------
__device__ __forceinline__ float h2dot(const __half2 a01, const __half2 a23,
                                       const __half2 xr01, const __half2 xr23,
                                       const __half2 neg2,
                                       const uint2 raw, float2* f01, float2* f23) {
    __half2 v01 = *(const __half2*)&raw.x, v23 = *(const __half2*)&raw.y;
    __half2 m01 = __hadd2(v01, xr01), m23 = __hadd2(v23, xr23);
    m01 = __hmax2(m01, __hmul2(m01, neg2));
    m23 = __hmax2(m23, __hmul2(m23, neg2));
    __half2 d2 = __hfma2(a23, m23, __hmul2(a01, m01));
    float2 df = __half22float2(d2);
    *f01 = __half22float2(v01);
    *f23 = __half22float2(v23);
    return df.x + df.y;
}

__global__ __launch_bounds__(256) void k_gat_edge(
    const __half* __restrict__ xlr, const float* __restrict__ att,
    const float* __restrict__ cbias,
    const float* __restrict__ hin, float* __restrict__ hout, __half* __restrict__ houth,
    const int* __restrict__ offs, const int* __restrict__ csr) {
    int half_ = threadIdx.x >> 7;
    int node = blockIdx.x * 2 + half_;
    int t128 = threadIdx.x & 127;
    int w = t128 >> 5, lane = threadIdx.x & 31;
    __shared__ float hacc[2][HEADS][HID];

    if (node < NN) {
        int beg = offs[node], end = offs[node + 1];
        const int off = w * HID + lane * 4;
        uint2 xrraw = *(const uint2*)(xlr + (size_t)node * 1024 + HOUT + off);
        const __half2 xr01 = *(const __half2*)&xrraw.x, xr23 = *(const __half2*)&xrraw.y;
        float4 a4 = *(const float4*)(att + w * HID + lane * 4);
        const __half2 a01 = __floats2half2_rn(a4.x, a4.y);
        const __half2 a23 = __floats2half2_rn(a4.z, a4.w);
        const __half2 neg2 = __float2half2_rn(NEG_SLOPE);

        float emax = -1e30f, denom = 0.f;
        float4 acc = make_float4(0.f, 0.f, 0.f, 0.f);
        int i = beg;
        for (; i + 3 < end; i += 4) {
            int s0 = __ldg(csr + i),     s1 = __ldg(csr + i + 1);
            int s2 = __ldg(csr + i + 2), s3 = __ldg(csr + i + 3);
            uint2 r0 = *(const uint2*)(xlr + (size_t)s0 * 1024 + off);
            uint2 r1 = *(const uint2*)(xlr + (size_t)s1 * 1024 + off);
            uint2 r2 = *(const uint2*)(xlr + (size_t)s2 * 1024 + off);
            uint2 r3 = *(const uint2*)(xlr + (size_t)s3 * 1024 + off);
            float2 v0a, v0b, v1a, v1b, v2a, v2b, v3a, v3b;
            float p0 = h2dot(a01, a23, xr01, xr23, neg2, r0, &v0a, &v0b);
            float p1 = h2dot(a01, a23, xr01, xr23, neg2, r1, &v1a, &v1b);
            float p2 = h2dot(a01, a23, xr01, xr23, neg2, r2, &v2a, &v2b);
            float p3 = h2dot(a01, a23, xr01, xr23, neg2, r3, &v3a, &v3b);
            #pragma unroll
            for (int o = 16; o; o >>= 1) {
                p0 += __shfl_xor_sync(0xffffffffu, p0, o);
                p1 += __shfl_xor_sync(0xffffffffu, p1, o);
                p2 += __shfl_xor_sync(0xffffffffu, p2, o);
                p3 += __shfl_xor_sync(0xffffffffu, p3, o);
            }
            float nm = fmaxf(fmaxf(emax, fmaxf(p0, p1)), fmaxf(p2, p3));
            float sc = __expf(emax - nm);
            denom *= sc;
            acc.x *= sc; acc.y *= sc; acc.z *= sc; acc.w *= sc;
            emax = nm;
            float w0 = __expf(p0 - nm), w1 = __expf(p1 - nm);
            float w2 = __expf(p2 - nm), w3 = __expf(p3 - nm);
            denom += (w0 + w1) + (w2 + w3);
            acc.x += w0 * v0a.x + w1 * v1a.x + w2 * v2a.x + w3 * v3a.x;
            acc.y += w0 * v0a.y + w1 * v1a.y + w2 * v2a.y + w3 * v3a.y;
            acc.z += w0 * v0b.x + w1 * v1b.x + w2 * v2b.x + w3 * v3b.x;
            acc.w += w0 * v0b.y + w1 * v1b.y + w2 * v2b.y + w3 * v3b.y;
        }
        for (; i < end; i++) {
            int s0 = __ldg(csr + i);
            uint2 r0 = *(const uint2*)(xlr + (size_t)s0 * 1024 + off);
            float2 v0a, v0b;
            float p0 = h2dot(a01, a23, xr01, xr23, neg2, r0, &v0a, &v0b);
            #pragma unroll
            for (int o = 16; o; o >>= 1) p0 += __shfl_xor_sync(0xffffffffu, p0, o);
            float nm = fmaxf(emax, p0);
            float sc = __expf(emax - nm);
            denom *= sc;
            acc.x *= sc; acc.y *= sc; acc.z *= sc; acc.w *= sc;
            emax = nm;
            float w0 = __expf(p0 - nm);
            denom += w0;
            acc.x += w0 * v0a.x; acc.y += w0 * v0a.y;
            acc.z += w0 * v0b.x; acc.w += w0 * v0b.y;
        }
        float inv = denom > 0.f ? 1.f / denom : 0.f;
        hacc[half_][w][lane * 4 + 0] = acc.x * inv;
        hacc[half_][w][lane * 4 + 1] = acc.y * inv;
        hacc[half_][w][lane * 4 + 2] = acc.z * inv;
        hacc[half_][w][lane * 4 + 3] = acc.w * inv;
    }
    __syncthreads();
    if (node < NN) {
        float sv = (hacc[half_][0][t128] + hacc[half_][1][t128] +
                    hacc[half_][2][t128] + hacc[half_][3][t128]) * 0.25f
                 + cbias[t128] + hin[(size_t)node * HID + t128];
        sv = fmaxf(sv, 0.f);
        hout[(size_t)node * HID + t128] = sv;
        houth[(size_t)node * HID + t128] = __float2half(sv);
    }
}

// ---------------- final predictor head ----------------
__global__ void k_pred3(const float* __restrict__ z2, const float* __restrict__ W,
                        const float* __restrict__ b, float* __restrict__ out, int n) {
    int warp = (blockIdx.x * blockDim.x + threadIdx.x) >> 5;
    int lane = threadIdx.x & 31;
    if (warp >= n) return;
    const float* zr = z2 + (size_t)warp * 128;
    float p = zr[lane] * W[lane] + zr[lane + 32] * W[lane + 32];
    #pragma unroll
    for (int o = 16; o; o >>= 1) p += __shfl_xor_sync(0xffffffffu, p, o);
    if (lane == 0) {
        float s = p + b[0];
        s = fminf(fmaxf(s, -15.f), 15.f);
        out[warp] = s;
    }
}

// ---------------- launch ----------------
extern "C" void kernel_launch(void* const* d_in, const int* in_sizes, int n_in,
                              void* d_out, int out_size) {
    const float* x      = (const float*)d_in[0];
    const int*   eidx   = (const int*)d_in[1];
    const float* emb_W  = (const float*)d_in[3];
    const float* emb_b  = (const float*)d_in[4];
    const float* Wl     = (const float*)d_in[5];
    const float* bl     = (const float*)d_in[6];
    const float* Wr     = (const float*)d_in[7];
    const float* br     = (const float*)d_in[8];
    const float* att    = (const float*)d_in[9];
    const float* cbias  = (const float*)d_in[10];
    const float* p1_W   = (const float*)d_in[11];
    const float* p1_b   = (const float*)d_in[12];
    const float* p2_W   = (const float*)d_in[13];
    const float* p2_b   = (const float*)d_in[14];
    const float* p3_W   = (const float*)d_in[15];
    const float* p3_b   = (const float*)d_in[16];
    float* out = (float*)d_out;

    const int* srcp = eidx;
    const int* dstp = eidx + EE;

    float *hA, *hB, *zf, *bB, *p2b;
    __half *hAh, *hBh, *xh, *xlrh;
    uint32_t* img;
    int *deg, *offs, *cursor, *csr, *blksum, *blkoff;
    cudaGetSymbolAddress((void**)&hA, g_hA);
    cudaGetSymbolAddress((void**)&hB, g_hB);
    cudaGetSymbolAddress((void**)&hAh, g_hAh);
    cudaGetSymbolAddress((void**)&hBh, g_hBh);
    cudaGetSymbolAddress((void**)&xh, g_xh);
    cudaGetSymbolAddress((void**)&xlrh, g_xlrh);
    cudaGetSymbolAddress((void**)&zf, g_zf);
    cudaGetSymbolAddress((void**)&img, g_img);
    cudaGetSymbolAddress((void**)&bB, g_bB);
    cudaGetSymbolAddress((void**)&p2b, g_p2b);
    cudaGetSymbolAddress((void**)&deg, g_deg);
    cudaGetSymbolAddress((void**)&offs, g_offs);
    cudaGetSymbolAddress((void**)&cursor, g_cursor);
    cudaGetSymbolAddress((void**)&csr, g_csr);
    cudaGetSymbolAddress((void**)&blksum, g_blksum);
    cudaGetSymbolAddress((void**)&blkoff, g_blkoff);

    cudaFuncSetAttribute(k_gemm6<64, 0>,  cudaFuncAttributeMaxDynamicSharedMemorySize, G5_SMEM);
    cudaFuncSetAttribute(k_gemm6<128, 0>, cudaFuncAttributeMaxDynamicSharedMemorySize, G5_SMEM);
    cudaFuncSetAttribute(k_gemm6<128, 1>, cudaFuncAttributeMaxDynamicSharedMemorySize, G5_SMEM);

    const int MB = (NN + 127) / 128;  // 391

    // (1) fp16 fragment images + bias packing
    k_img<<<(IMG_TOTAL + 255) / 256, 256>>>(emb_W, Wl, Wr, p1_W, p2_W, bl, br, p2_b,
                                            img, bB, p2b);
    // (2) x -> fp16
    k_h2<<<(NN * FIN + 255) / 256, 256>>>(x, xh, NN * FIN);
    // (3) embedding
    k_gemm6<64, 0><<<dim3(MB, 1), 256, 2 * STAGE_B>>>(xh, img + IMG_EMB, emb_b, hA, hAh, NN, HID, 1);
    // (4) layer-1 split GEMM  <-- profiled slot
    k_gemm6<128, 1><<<dim3(MB, 8), 256, 4 * STAGE_B>>>(hAh, img + IMG_WB, bB, nullptr, xlrh, NN, 1024, 0);
    // CSR build
    k_zero_int<<<(NN + 255) / 256, 256>>>(deg, NN);
    k_count_deg<<<(EE + 255) / 256, 256>>>(dstp, deg, EE);
    k_scan_part<<<NBLK, SCAN_B>>>(deg, offs, blksum, NN);
    k_scan_blk<<<1, 64>>>(blksum, blkoff, offs, NBLK, NN);
    k_scan_add<<<NBLK, SCAN_B>>>(offs, blkoff, cursor, NN);
    k_fill_csr<<<(EE + 255) / 256, 256>>>(srcp, dstp, cursor, csr, EE);

    // layer 1 edge
    float* hc = hA;   __half* hch = hAh;
    float* hn = hB;   __half* hnh = hBh;
    k_gat_edge<<<(NN + 1) / 2, 256>>>(xlrh, att, cbias, hc, hn, hnh, offs, csr);
    { float* t = hc; hc = hn; hn = t; __half* th = hch; hch = hnh; hnh = th; }

    // layers 2..3
    for (int l = 1; l < LAYERS; l++) {
        k_gemm6<128, 1><<<dim3(MB, 8), 256, 4 * STAGE_B>>>(
            hch, img + IMG_WB + (size_t)l * 65536, bB + (size_t)l * 1024, nullptr, xlrh, NN, 1024, 0);
        k_gat_edge<<<(NN + 1) / 2, 256>>>(xlrh, att + (size_t)l * HEADS * HID,
                                          cbias + l * HID, hc, hn, hnh, offs, csr);
        float* t = hc; hc = hn; hn = t; __half* th = hch; hch = hnh; hnh = th;
    }

    // predictor MLP
    float* z1f = zf;
    __half* z1h = xlrh;
    float* z2 = zf + (size_t)NN * HID;
    k_gemm6<128, 0><<<dim3(MB, 1), 256, 4 * STAGE_B>>>(hch, img + IMG_P1, p1_b, z1f, z1h, NN, HID, 1);
    k_gemm6<128, 0><<<dim3(MB, 1), 256, 4 * STAGE_B>>>(z1h, img + IMG_P2, p2b, z2, nullptr, NN, HID, 1);
    k_pred3<<<(NN * 32 + 255) / 256, 256>>>(z2, p3_W, p3_b, out, NN);
}

// round 15
// speedup vs baseline: 1.2148x; 1.0188x over previous
#include <cuda_runtime.h>
#include <cuda_fp16.h>
#include <math.h>
#include <stdint.h>

#define NN   50000
#define EE   800000
#define FIN  64
#define HID  128
#define HEADS 4
#define HOUT 512
#define LAYERS 3
#define NEG_SLOPE 0.2f
#define SCAN_B 1024
#define NBLK ((NN + SCAN_B - 1) / SCAN_B)

#define IMG_EMB 0
#define IMG_WB  4096
#define IMG_P1  (4096 + 3 * 65536)
#define IMG_P2  (IMG_P1 + 8192)
#define IMG_TOTAL (IMG_P2 + 8192)

// ---------------- scratch ----------------
__device__ float    g_hA[(size_t)NN * HID];
__device__ float    g_hB[(size_t)NN * HID];
__device__ __half   g_hAh[(size_t)NN * HID];
__device__ __half   g_hBh[(size_t)NN * HID];
__device__ __half   g_xh[(size_t)NN * FIN];
__device__ __half   g_xlrh[(size_t)NN * 1024];
__device__ float    g_zf[(size_t)NN * 256];
__device__ uint32_t g_img[IMG_TOTAL];
__device__ float    g_bB[(size_t)LAYERS * 1024];
__device__ float    g_p2b[128];
__device__ int      g_deg[NN];
__device__ int      g_offs[NN + 1];
__device__ int      g_cursor[NN];
__device__ int      g_csr[EE];
__device__ int      g_blksum[NBLK];
__device__ int      g_blkoff[NBLK];

__device__ __forceinline__ void mma_f16(float* d, const uint32_t* a, const uint32_t* b) {
    asm volatile(
        "mma.sync.aligned.m16n8k16.row.col.f32.f16.f16.f32 "
        "{%0,%1,%2,%3}, {%4,%5,%6,%7}, {%8,%9}, {%0,%1,%2,%3};"
        : "+f"(d[0]), "+f"(d[1]), "+f"(d[2]), "+f"(d[3])
        : "r"(a[0]), "r"(a[1]), "r"(a[2]), "r"(a[3]), "r"(b[0]), "r"(b[1]));
}
__device__ __forceinline__ uint32_t smem_u32(const void* p) {
    uint32_t a;
    asm("{ .reg .u64 t; cvta.to.shared.u64 t, %1; cvt.u32.u64 %0, t; }" : "=r"(a) : "l"(p));
    return a;
}

// ---------------- prep: fp16 B fragment images + bias packing ----------------
__global__ void k_img(const float* __restrict__ emb_W, const float* __restrict__ Wl,
                      const float* __restrict__ Wr, const float* __restrict__ p1_W,
                      const float* __restrict__ p2_W,
                      const float* __restrict__ bl, const float* __restrict__ br,
                      const float* __restrict__ p2_b,
                      uint32_t* __restrict__ img, float* __restrict__ bB,
                      float* __restrict__ p2bp) {
    int w = blockIdx.x * blockDim.x + threadIdx.x;
    if (w >= IMG_TOTAL) return;
    if (w < LAYERS * 1024) {
        int l = w / 1024, n = w % 1024;
        bB[w] = (n < HOUT) ? bl[l * HOUT + n] : br[l * HOUT + n - HOUT];
    }
    if (w < 128) p2bp[w] = (w < 64) ? p2_b[w] : 0.f;

    int rem, nc, seg;
    if (w < IMG_WB)      { seg = 0; rem = w;           nc = 2; }
    else if (w < IMG_P1) { seg = 1; rem = w - IMG_WB;  nc = 4; }
    else if (w < IMG_P2) { seg = 2; rem = w - IMG_P1;  nc = 4; }
    else                 { seg = 3; rem = w - IMG_P2;  nc = 4; }
    int layer = 0;
    if (seg == 1) { layer = rem / 65536; rem %= 65536; }
    int cw = nc * 2048;
    int blk = rem / cw;
    int r2 = rem % cw;
    int kc = r2 / 2048;
    int u = r2 % 2048;
    int comp = u & 3;
    int lane = (u >> 2) & 31;
    int g = u >> 7;
    int lig = lane & 3, grp = lane >> 2;
    int k16 = comp >> 1, pairsel = comp & 1;
    int k = kc * 32 + k16 * 16 + pairsel * 8 + lig * 2;
    int n = blk * 128 + g * 8 + grp;
    float lo, hi;
    if (seg == 0) {
        lo = emb_W[k * HID + n];
        hi = emb_W[(k + 1) * HID + n];
    } else if (seg == 1) {
        if (n < HOUT) {
            lo = Wl[((size_t)layer * HID + k) * HOUT + n];
            hi = Wl[((size_t)layer * HID + k + 1) * HOUT + n];
        } else {
            lo = Wr[((size_t)layer * HID + k) * HOUT + (n - HOUT)];
            hi = Wr[((size_t)layer * HID + k + 1) * HOUT + (n - HOUT)];
        }
    } else if (seg == 2) {
        lo = p1_W[k * HID + n];
        hi = p1_W[(k + 1) * HID + n];
    } else {
        lo = (n < 64) ? p2_W[k * 64 + n] : 0.f;
        hi = (n < 64) ? p2_W[(k + 1) * 64 + n] : 0.f;
    }
    __half2 h2 = __floats2half2_rn(lo, hi);
    img[w] = *(uint32_t*)&h2;
}

__global__ void k_h2(const float* __restrict__ x, __half* __restrict__ xh, int n) {
    int i = blockIdx.x * blockDim.x + threadIdx.x;
    if (i < n) xh[i] = __float2half(x[i]);
}

// ---------------- CSR build ----------------
__global__ void k_zero_int(int* p, int n) {
    int i = blockIdx.x * blockDim.x + threadIdx.x;
    if (i < n) p[i] = 0;
}
__global__ void k_count_deg(const int* __restrict__ dst, int* __restrict__ deg, int e) {
    int i = blockIdx.x * blockDim.x + threadIdx.x;
    if (i < e) atomicAdd(&deg[dst[i]], 1);
}
__global__ void k_scan_part(const int* __restrict__ deg, int* __restrict__ offs,
                            int* __restrict__ blksum, int n) {
    __shared__ int wsum[32];
    int gid = blockIdx.x * SCAN_B + threadIdx.x;
    int lane = threadIdx.x & 31, wid = threadIdx.x >> 5;
    int v = (gid < n) ? deg[gid] : 0;
    int s = v;
    #pragma unroll
    for (int o = 1; o < 32; o <<= 1) {
        int t = __shfl_up_sync(0xffffffffu, s, o);
        if (lane >= o) s += t;
    }
    if (lane == 31) wsum[wid] = s;
    __syncthreads();
    if (wid == 0) {
        int ws = wsum[lane];
        #pragma unroll
        for (int o = 1; o < 32; o <<= 1) {
            int t = __shfl_up_sync(0xffffffffu, ws, o);
            if (lane >= o) ws += t;
        }
        wsum[lane] = ws;
    }
    __syncthreads();
    int base = wid ? wsum[wid - 1] : 0;
    int incl = base + s;
    if (gid < n) offs[gid] = incl - v;
    if (threadIdx.x == SCAN_B - 1) blksum[blockIdx.x] = incl;
}
__global__ void k_scan_blk(const int* __restrict__ blksum, int* __restrict__ blkoff,
                           int* __restrict__ offs, int nblk, int n) {
    __shared__ int sm[64];
    int t = threadIdx.x;
    int v = (t < nblk) ? blksum[t] : 0;
    sm[t] = v;
    __syncthreads();
    #pragma unroll
    for (int d = 1; d < 64; d <<= 1) {
        int tv = (t >= d) ? sm[t - d] : 0;
        __syncthreads();
        sm[t] += tv;
        __syncthreads();
    }
    if (t < nblk) blkoff[t] = sm[t] - v;
    if (t == 63) offs[n] = sm[63];
}
__global__ void k_scan_add(int* __restrict__ offs, const int* __restrict__ blkoff,
                           int* __restrict__ cursor, int n) {
    int gid = blockIdx.x * SCAN_B + threadIdx.x;
    if (gid < n) {
        int o = offs[gid] + blkoff[blockIdx.x];
        offs[gid] = o;
        cursor[gid] = o;
    }
}
__global__ void k_fill_csr(const int* __restrict__ src, const int* __restrict__ dst,
                           int* __restrict__ cursor, int* __restrict__ csr, int e) {
    int i = blockIdx.x * blockDim.x + threadIdx.x;
    if (i < e) {
        int p = atomicAdd(&cursor[dst[i]], 1);
        csr[p] = src[i];
    }
}

// ---------------- GEMM v5 (R10 exact): fp16 mma, full-K cp.async pipeline ----------------
#define STAGE_B 18432
#define G5_SMEM (4 * STAGE_B)
#define CPWAIT(n) asm volatile("cp.async.wait_group " #n ";")

template <int KT, int MODE>
__global__ __launch_bounds__(128, 2) void k_gemm5(
    const __half* __restrict__ A, const uint32_t* __restrict__ img,
    const float* __restrict__ bias, float* __restrict__ C, __half* __restrict__ Ch,
    int M, int Ns, int relu) {
    extern __shared__ uint32_t sm[];
    constexpr int NK = KT / 32;
    int tid = threadIdx.x;
    int wid = tid >> 5, lane = tid & 31;
    int grp = lane >> 2, lig = lane & 3;
    const int wm = (wid & 1) * 64;
    const int wg8 = (wid >> 1) * 8;
    const int bm = blockIdx.x * 128, bn = blockIdx.y * 128;
    const uint32_t* imgB = img + (size_t)blockIdx.y * NK * 2048;
    uint32_t sbase = smem_u32(sm);

    float acc[4][8][4];
    #pragma unroll
    for (int i = 0; i < 4; i++)
        #pragma unroll
        for (int j = 0; j < 8; j++)
            #pragma unroll
            for (int q = 0; q < 4; q++) acc[i][j][q] = 0.f;

    auto stage = [&](int kc) {
        uint32_t abase = sbase + kc * STAGE_B;
        #pragma unroll
        for (int i = 0; i < 8; i++) {
            int idx = tid + i * 128;
            int r = idx >> 3, s = idx & 7;
            int gr = bm + r;
            uint32_t dst = abase + (uint32_t)(r * 80 + s * 8);
            const __half* src = A + (size_t)gr * KT + kc * 32 + s * 4;
            int sz = (gr < M) ? 8 : 0;
            asm volatile("cp.async.ca.shared.global [%0], [%1], 8, %2;"
                         :: "r"(dst), "l"(src), "r"(sz));
        }
        uint32_t bbase = abase + 2560 * 4;
        const uint32_t* bsrc = imgB + kc * 2048;
        #pragma unroll
        for (int i = 0; i < 4; i++) {
            int idx = tid + i * 128;
            uint32_t dst = bbase + (uint32_t)idx * 16;
            asm volatile("cp.async.ca.shared.global [%0], [%1], 16, 16;"
                         :: "r"(dst), "l"(bsrc + idx * 4));
        }
        asm volatile("cp.async.commit_group;");
    };

    #pragma unroll
    for (int kc = 0; kc < NK; kc++) stage(kc);

    auto compute = [&](int kc) {
        const uint32_t* As = sm + kc * 4608;
        const uint32_t* Bs = As + 2560;
        uint4 bq[8];
        #pragma unroll
        for (int nt = 0; nt < 8; nt++)
            bq[nt] = *(const uint4*)(Bs + ((wg8 + nt) * 32 + lane) * 4);
        #pragma unroll
        for (int k16 = 0; k16 < 2; k16++) {
            #pragma unroll
            for (int mt = 0; mt < 4; mt++) {
                int rw = (wm + mt * 16 + grp) * 20 + k16 * 8 + lig;
                uint32_t av[4];
                av[0] = As[rw];
                av[1] = As[rw + 160];
                av[2] = As[rw + 4];
                av[3] = As[rw + 164];
                #pragma unroll
                for (int nt = 0; nt < 8; nt++) {
                    uint32_t bv[2];
                    if (k16 == 0) { bv[0] = bq[nt].x; bv[1] = bq[nt].y; }
                    else          { bv[0] = bq[nt].z; bv[1] = bq[nt].w; }
                    mma_f16(acc[mt][nt], av, bv);
                }
            }
        }
    };

    if (NK == 4) {
        CPWAIT(3); __syncthreads(); compute(0);
        CPWAIT(2); __syncthreads(); compute(1);
        CPWAIT(1); __syncthreads(); compute(2);
        CPWAIT(0); __syncthreads(); compute(3);
    } else {
        CPWAIT(1); __syncthreads(); compute(0);
        CPWAIT(0); __syncthreads(); compute(1);
    }

    #pragma unroll
    for (int mt = 0; mt < 4; mt++) {
        #pragma unroll
        for (int nt = 0; nt < 8; nt++) {
            int col = bn + (wg8 + nt) * 8 + lig * 2;
            float b0 = __ldg(bias + col), b1 = __ldg(bias + col + 1);
            int row0 = bm + wm + mt * 16 + grp;
            int row1 = row0 + 8;
            float v0 = acc[mt][nt][0] + b0;
            float v1 = acc[mt][nt][1] + b1;
            float v2 = acc[mt][nt][2] + b0;
            float v3 = acc[mt][nt][3] + b1;
            if (relu) {
                v0 = fmaxf(v0, 0.f); v1 = fmaxf(v1, 0.f);
                v2 = fmaxf(v2, 0.f); v3 = fmaxf(v3, 0.f);
            }
            if (MODE == 0) {
                if (row0 < M) {
                    *(float2*)(C + (size_t)row0 * Ns + col) = make_float2(v0, v1);
                    if (Ch) *(__half2*)(Ch + (size_t)row0 * Ns + col) = __floats2half2_rn(v0, v1);
                }
                if (row1 < M) {
                    *(float2*)(C + (size_t)row1 * Ns + col) = make_float2(v2, v3);
                    if (Ch) *(__half2*)(Ch + (size_t)row1 * Ns + col) = __floats2half2_rn(v2, v3);
                }
            } else {
                if (row0 < M) *(__half2*)(Ch + (size_t)row0 * 1024 + col) = __floats2half2_rn(v0, v1);
                if (row1 < M) *(__half2*)(Ch + (size_t)row1 * 1024 + col) = __floats2half2_rn(v2, v3);
            }
        }
    }
}

// ---------------- GATv2 edge kernel (R10 exact): fp16 xl|xr, 4-way online softmax ----------------
__device__ __forceinline__ float h2dot(const __half2 a01, const __half2 a23,
                                       const __half2 xr01, const __half2 xr23,
                                       const __half2 neg2,
                                       const uint2 raw, float2* f01, float2* f23) {
    __half2 v01 = *(const __half2*)&raw.x, v23 = *(const __half2*)&raw.y;
    __half2 m01 = __hadd2(v01, xr01), m23 = __hadd2(v23, xr23);
    m01 = __hmax2(m01, __hmul2(m01, neg2));
    m23 = __hmax2(m23, __hmul2(m23, neg2));
    __half2 d2 = __hfma2(a23, m23, __hmul2(a01, m01));
    float2 df = __half22float2(d2);
    *f01 = __half22float2(v01);
    *f23 = __half22float2(v23);
    return df.x + df.y;
}

__global__ __launch_bounds__(256) void k_gat_edge(
    const __half* __restrict__ xlr, const float* __restrict__ att,
    const float* __restrict__ cbias,
    const float* __restrict__ hin, float* __restrict__ hout, __half* __restrict__ houth,
    const int* __restrict__ offs, const int* __restrict__ csr) {
    int half_ = threadIdx.x >> 7;
    int node = blockIdx.x * 2 + half_;
    int t128 = threadIdx.x & 127;
    int w = t128 >> 5, lane = threadIdx.x & 31;
    __shared__ float hacc[2][HEADS][HID];

    if (node < NN) {
        int beg = offs[node], end = offs[node + 1];
        const int off = w * HID + lane * 4;
        uint2 xrraw = *(const uint2*)(xlr + (size_t)node * 1024 + HOUT + off);
        const __half2 xr01 = *(const __half2*)&xrraw.x, xr23 = *(const __half2*)&xrraw.y;
        float4 a4 = *(const float4*)(att + w * HID + lane * 4);
        const __half2 a01 = __floats2half2_rn(a4.x, a4.y);
        const __half2 a23 = __floats2half2_rn(a4.z, a4.w);
        const __half2 neg2 = __float2half2_rn(NEG_SLOPE);

        float emax = -1e30f, denom = 0.f;
        float4 acc = make_float4(0.f, 0.f, 0.f, 0.f);
        int i = beg;
        for (; i + 3 < end; i += 4) {
            int s0 = __ldg(csr + i),     s1 = __ldg(csr + i + 1);
            int s2 = __ldg(csr + i + 2), s3 = __ldg(csr + i + 3);
            uint2 r0 = *(const uint2*)(xlr + (size_t)s0 * 1024 + off);
            uint2 r1 = *(const uint2*)(xlr + (size_t)s1 * 1024 + off);
            uint2 r2 = *(const uint2*)(xlr + (size_t)s2 * 1024 + off);
            uint2 r3 = *(const uint2*)(xlr + (size_t)s3 * 1024 + off);
            float2 v0a, v0b, v1a, v1b, v2a, v2b, v3a, v3b;
            float p0 = h2dot(a01, a23, xr01, xr23, neg2, r0, &v0a, &v0b);
            float p1 = h2dot(a01, a23, xr01, xr23, neg2, r1, &v1a, &v1b);
            float p2 = h2dot(a01, a23, xr01, xr23, neg2, r2, &v2a, &v2b);
            float p3 = h2dot(a01, a23, xr01, xr23, neg2, r3, &v3a, &v3b);
            #pragma unroll
            for (int o = 16; o; o >>= 1) {
                p0 += __shfl_xor_sync(0xffffffffu, p0, o);
                p1 += __shfl_xor_sync(0xffffffffu, p1, o);
                p2 += __shfl_xor_sync(0xffffffffu, p2, o);
                p3 += __shfl_xor_sync(0xffffffffu, p3, o);
            }
            float nm = fmaxf(fmaxf(emax, fmaxf(p0, p1)), fmaxf(p2, p3));
            float sc = __expf(emax - nm);
            denom *= sc;
            acc.x *= sc; acc.y *= sc; acc.z *= sc; acc.w *= sc;
            emax = nm;
            float w0 = __expf(p0 - nm), w1 = __expf(p1 - nm);
            float w2 = __expf(p2 - nm), w3 = __expf(p3 - nm);
            denom += (w0 + w1) + (w2 + w3);
            acc.x += w0 * v0a.x + w1 * v1a.x + w2 * v2a.x + w3 * v3a.x;
            acc.y += w0 * v0a.y + w1 * v1a.y + w2 * v2a.y + w3 * v3a.y;
            acc.z += w0 * v0b.x + w1 * v1b.x + w2 * v2b.x + w3 * v3b.x;
            acc.w += w0 * v0b.y + w1 * v1b.y + w2 * v2b.y + w3 * v3b.y;
        }
        for (; i < end; i++) {
            int s0 = __ldg(csr + i);
            uint2 r0 = *(const uint2*)(xlr + (size_t)s0 * 1024 + off);
            float2 v0a, v0b;
            float p0 = h2dot(a01, a23, xr01, xr23, neg2, r0, &v0a, &v0b);
            #pragma unroll
            for (int o = 16; o; o >>= 1) p0 += __shfl_xor_sync(0xffffffffu, p0, o);
            float nm = fmaxf(emax, p0);
            float sc = __expf(emax - nm);
            denom *= sc;
            acc.x *= sc; acc.y *= sc; acc.z *= sc; acc.w *= sc;
            emax = nm;
            float w0 = __expf(p0 - nm);
            denom += w0;
            acc.x += w0 * v0a.x; acc.y += w0 * v0a.y;
            acc.z += w0 * v0b.x; acc.w += w0 * v0b.y;
        }
        float inv = denom > 0.f ? 1.f / denom : 0.f;
        hacc[half_][w][lane * 4 + 0] = acc.x * inv;
        hacc[half_][w][lane * 4 + 1] = acc.y * inv;
        hacc[half_][w][lane * 4 + 2] = acc.z * inv;
        hacc[half_][w][lane * 4 + 3] = acc.w * inv;
    }
    __syncthreads();
    if (node < NN) {
        float sv = (hacc[half_][0][t128] + hacc[half_][1][t128] +
                    hacc[half_][2][t128] + hacc[half_][3][t128]) * 0.25f
                 + cbias[t128] + hin[(size_t)node * HID + t128];
        sv = fmaxf(sv, 0.f);
        hout[(size_t)node * HID + t128] = sv;
        houth[(size_t)node * HID + t128] = __float2half(sv);
    }
}

// ---------------- final predictor head ----------------
__global__ void k_pred3(const float* __restrict__ z2, const float* __restrict__ W,
                        const float* __restrict__ b, float* __restrict__ out, int n) {
    int warp = (blockIdx.x * blockDim.x + threadIdx.x) >> 5;
    int lane = threadIdx.x & 31;
    if (warp >= n) return;
    const float* zr = z2 + (size_t)warp * 128;
    float p = zr[lane] * W[lane] + zr[lane + 32] * W[lane + 32];
    #pragma unroll
    for (int o = 16; o; o >>= 1) p += __shfl_xor_sync(0xffffffffu, p, o);
    if (lane == 0) {
        float s = p + b[0];
        s = fminf(fmaxf(s, -15.f), 15.f);
        out[warp] = s;
    }
}

// ---------------- launch ----------------
extern "C" void kernel_launch(void* const* d_in, const int* in_sizes, int n_in,
                              void* d_out, int out_size) {
    const float* x      = (const float*)d_in[0];
    const int*   eidx   = (const int*)d_in[1];
    const float* emb_W  = (const float*)d_in[3];
    const float* emb_b  = (const float*)d_in[4];
    const float* Wl     = (const float*)d_in[5];
    const float* bl     = (const float*)d_in[6];
    const float* Wr     = (const float*)d_in[7];
    const float* br     = (const float*)d_in[8];
    const float* att    = (const float*)d_in[9];
    const float* cbias  = (const float*)d_in[10];
    const float* p1_W   = (const float*)d_in[11];
    const float* p1_b   = (const float*)d_in[12];
    const float* p2_W   = (const float*)d_in[13];
    const float* p2_b   = (const float*)d_in[14];
    const float* p3_W   = (const float*)d_in[15];
    const float* p3_b   = (const float*)d_in[16];
    float* out = (float*)d_out;

    const int* srcp = eidx;
    const int* dstp = eidx + EE;

    float *hA, *hB, *zf, *bB, *p2b;
    __half *hAh, *hBh, *xh, *xlrh;
    uint32_t* img;
    int *deg, *offs, *cursor, *csr, *blksum, *blkoff;
    cudaGetSymbolAddress((void**)&hA, g_hA);
    cudaGetSymbolAddress((void**)&hB, g_hB);
    cudaGetSymbolAddress((void**)&hAh, g_hAh);
    cudaGetSymbolAddress((void**)&hBh, g_hBh);
    cudaGetSymbolAddress((void**)&xh, g_xh);
    cudaGetSymbolAddress((void**)&xlrh, g_xlrh);
    cudaGetSymbolAddress((void**)&zf, g_zf);
    cudaGetSymbolAddress((void**)&img, g_img);
    cudaGetSymbolAddress((void**)&bB, g_bB);
    cudaGetSymbolAddress((void**)&p2b, g_p2b);
    cudaGetSymbolAddress((void**)&deg, g_deg);
    cudaGetSymbolAddress((void**)&offs, g_offs);
    cudaGetSymbolAddress((void**)&cursor, g_cursor);
    cudaGetSymbolAddress((void**)&csr, g_csr);
    cudaGetSymbolAddress((void**)&blksum, g_blksum);
    cudaGetSymbolAddress((void**)&blkoff, g_blkoff);

    cudaFuncSetAttribute(k_gemm5<64, 0>,  cudaFuncAttributeMaxDynamicSharedMemorySize, G5_SMEM);
    cudaFuncSetAttribute(k_gemm5<128, 0>, cudaFuncAttributeMaxDynamicSharedMemorySize, G5_SMEM);
    cudaFuncSetAttribute(k_gemm5<128, 1>, cudaFuncAttributeMaxDynamicSharedMemorySize, G5_SMEM);

    const int MB = (NN + 127) / 128;  // 391

    // ---- fork a side stream for the independent CSR build ----
    cudaStream_t s2;
    cudaStreamCreateWithFlags(&s2, cudaStreamNonBlocking);
    cudaEvent_t evFork, evJoin;
    cudaEventCreateWithFlags(&evFork, cudaEventDisableTiming);
    cudaEventCreateWithFlags(&evJoin, cudaEventDisableTiming);

    cudaEventRecord(evFork, 0);
    cudaStreamWaitEvent(s2, evFork, 0);

    // side stream: CSR build (independent of everything on the main stream)
    k_zero_int<<<(NN + 255) / 256, 256, 0, s2>>>(deg, NN);
    k_count_deg<<<(EE + 255) / 256, 256, 0, s2>>>(dstp, deg, EE);
    k_scan_part<<<NBLK, SCAN_B, 0, s2>>>(deg, offs, blksum, NN);
    k_scan_blk<<<1, 64, 0, s2>>>(blksum, blkoff, offs, NBLK, NN);
    k_scan_add<<<NBLK, SCAN_B, 0, s2>>>(offs, blkoff, cursor, NN);
    k_fill_csr<<<(EE + 255) / 256, 256, 0, s2>>>(srcp, dstp, cursor, csr, EE);
    cudaEventRecord(evJoin, s2);

    // main stream: prep + embedding + layer-1 GEMM (concurrent with CSR build)
    k_img<<<(IMG_TOTAL + 255) / 256, 256>>>(emb_W, Wl, Wr, p1_W, p2_W, bl, br, p2_b,
                                            img, bB, p2b);
    k_h2<<<(NN * FIN + 255) / 256, 256>>>(x, xh, NN * FIN);
    k_gemm5<64, 0><<<dim3(MB, 1), 128, 2 * STAGE_B>>>(xh, img + IMG_EMB, emb_b, hA, hAh, NN, HID, 1);
    k_gemm5<128, 1><<<dim3(MB, 8), 128, 4 * STAGE_B>>>(hAh, img + IMG_WB, bB, nullptr, xlrh, NN, 1024, 0);

    // join: edge kernel needs both xlr (main) and csr (side)
    cudaStreamWaitEvent(0, evJoin, 0);

    // layer 1 edge
    float* hc = hA;   __half* hch = hAh;
    float* hn = hB;   __half* hnh = hBh;
    k_gat_edge<<<(NN + 1) / 2, 256>>>(xlrh, att, cbias, hc, hn, hnh, offs, csr);
    { float* t = hc; hc = hn; hn = t; __half* th = hch; hch = hnh; hnh = th; }

    // layers 2..3
    for (int l = 1; l < LAYERS; l++) {
        k_gemm5<128, 1><<<dim3(MB, 8), 128, 4 * STAGE_B>>>(
            hch, img + IMG_WB + (size_t)l * 65536, bB + (size_t)l * 1024, nullptr, xlrh, NN, 1024, 0);
        k_gat_edge<<<(NN + 1) / 2, 256>>>(xlrh, att + (size_t)l * HEADS * HID,
                                          cbias + l * HID, hc, hn, hnh, offs, csr);
        float* t = hc; hc = hn; hn = t; __half* th = hch; hch = hnh; hnh = th;
    }

    // predictor MLP
    float* z1f = zf;
    __half* z1h = xlrh;
    float* z2 = zf + (size_t)NN * HID;
    k_gemm5<128, 0><<<dim3(MB, 1), 128, 4 * STAGE_B>>>(hch, img + IMG_P1, p1_b, z1f, z1h, NN, HID, 1);
    k_gemm5<128, 0><<<dim3(MB, 1), 128, 4 * STAGE_B>>>(z1h, img + IMG_P2, p2b, z2, nullptr, NN, HID, 1);
    k_pred3<<<(NN * 32 + 255) / 256, 256>>>(z2, p3_W, p3_b, out, NN);

    cudaEventDestroy(evFork);
    cudaEventDestroy(evJoin);
    cudaStreamDestroy(s2);
}

// round 16
// speedup vs baseline: 1.2469x; 1.0264x over previous
#include <cuda_runtime.h>
#include <cuda_fp16.h>
#include <math.h>
#include <stdint.h>

#define NN   50000
#define EE   800000
#define FIN  64
#define HID  128
#define HEADS 4
#define HOUT 512
#define LAYERS 3
#define NEG_SLOPE 0.2f
#define SCAN_B 1024
#define NBLK ((NN + SCAN_B - 1) / SCAN_B)

#define IMG_EMB 0
#define IMG_WB  4096
#define IMG_P1  (4096 + 3 * 65536)
#define IMG_P2  (IMG_P1 + 8192)
#define IMG_TOTAL (IMG_P2 + 8192)

// ---------------- scratch ----------------
__device__ float    g_hA[(size_t)NN * HID];
__device__ float    g_hB[(size_t)NN * HID];
__device__ __half   g_hAh[(size_t)NN * HID];
__device__ __half   g_hBh[(size_t)NN * HID];
__device__ __half   g_xh[(size_t)NN * FIN];
__device__ __half   g_xlrh[(size_t)NN * 1024];
__device__ uint32_t g_img[IMG_TOTAL];
__device__ float    g_bB[(size_t)LAYERS * 1024];
__device__ float    g_p2b[128];
__device__ int      g_deg[NN];
__device__ int      g_offs[NN + 1];
__device__ int      g_cursor[NN];
__device__ int      g_csr[EE];
__device__ int      g_blksum[NBLK];
__device__ int      g_blkoff[NBLK];

__device__ __forceinline__ void mma_f16(float* d, const uint32_t* a, const uint32_t* b) {
    asm volatile(
        "mma.sync.aligned.m16n8k16.row.col.f32.f16.f16.f32 "
        "{%0,%1,%2,%3}, {%4,%5,%6,%7}, {%8,%9}, {%0,%1,%2,%3};"
        : "+f"(d[0]), "+f"(d[1]), "+f"(d[2]), "+f"(d[3])
        : "r"(a[0]), "r"(a[1]), "r"(a[2]), "r"(a[3]), "r"(b[0]), "r"(b[1]));
}
__device__ __forceinline__ uint32_t smem_u32(const void* p) {
    uint32_t a;
    asm("{ .reg .u64 t; cvta.to.shared.u64 t, %1; cvt.u32.u64 %0, t; }" : "=r"(a) : "l"(p));
    return a;
}

// ---------------- prep: fp16 B fragment images + bias packing ----------------
__global__ void k_img(const float* __restrict__ emb_W, const float* __restrict__ Wl,
                      const float* __restrict__ Wr, const float* __restrict__ p1_W,
                      const float* __restrict__ p2_W,
                      const float* __restrict__ bl, const float* __restrict__ br,
                      const float* __restrict__ p2_b,
                      uint32_t* __restrict__ img, float* __restrict__ bB,
                      float* __restrict__ p2bp) {
    int w = blockIdx.x * blockDim.x + threadIdx.x;
    if (w >= IMG_TOTAL) return;
    if (w < LAYERS * 1024) {
        int l = w / 1024, n = w % 1024;
        bB[w] = (n < HOUT) ? bl[l * HOUT + n] : br[l * HOUT + n - HOUT];
    }
    if (w < 128) p2bp[w] = (w < 64) ? p2_b[w] : 0.f;

    int rem, nc, seg;
    if (w < IMG_WB)      { seg = 0; rem = w;           nc = 2; }
    else if (w < IMG_P1) { seg = 1; rem = w - IMG_WB;  nc = 4; }
    else if (w < IMG_P2) { seg = 2; rem = w - IMG_P1;  nc = 4; }
    else                 { seg = 3; rem = w - IMG_P2;  nc = 4; }
    int layer = 0;
    if (seg == 1) { layer = rem / 65536; rem %= 65536; }
    int cw = nc * 2048;
    int blk = rem / cw;
    int r2 = rem % cw;
    int kc = r2 / 2048;
    int u = r2 % 2048;
    int comp = u & 3;
    int lane = (u >> 2) & 31;
    int g = u >> 7;
    int lig = lane & 3, grp = lane >> 2;
    int k16 = comp >> 1, pairsel = comp & 1;
    int k = kc * 32 + k16 * 16 + pairsel * 8 + lig * 2;
    int n = blk * 128 + g * 8 + grp;
    float lo, hi;
    if (seg == 0) {
        lo = emb_W[k * HID + n];
        hi = emb_W[(k + 1) * HID + n];
    } else if (seg == 1) {
        if (n < HOUT) {
            lo = Wl[((size_t)layer * HID + k) * HOUT + n];
            hi = Wl[((size_t)layer * HID + k + 1) * HOUT + n];
        } else {
            lo = Wr[((size_t)layer * HID + k) * HOUT + (n - HOUT)];
            hi = Wr[((size_t)layer * HID + k + 1) * HOUT + (n - HOUT)];
        }
    } else if (seg == 2) {
        lo = p1_W[k * HID + n];
        hi = p1_W[(k + 1) * HID + n];
    } else {
        lo = (n < 64) ? p2_W[k * 64 + n] : 0.f;
        hi = (n < 64) ? p2_W[(k + 1) * 64 + n] : 0.f;
    }
    __half2 h2 = __floats2half2_rn(lo, hi);
    img[w] = *(uint32_t*)&h2;
}

__global__ void k_h2(const float* __restrict__ x, __half* __restrict__ xh, int n) {
    int i = blockIdx.x * blockDim.x + threadIdx.x;
    if (i < n) xh[i] = __float2half(x[i]);
}

// ---------------- CSR build ----------------
__global__ void k_zero_int(int* p, int n) {
    int i = blockIdx.x * blockDim.x + threadIdx.x;
    if (i < n) p[i] = 0;
}
__global__ void k_count_deg(const int* __restrict__ dst, int* __restrict__ deg, int e) {
    int i = blockIdx.x * blockDim.x + threadIdx.x;
    if (i < e) atomicAdd(&deg[dst[i]], 1);
}
__global__ void k_scan_part(const int* __restrict__ deg, int* __restrict__ offs,
                            int* __restrict__ blksum, int n) {
    __shared__ int wsum[32];
    int gid = blockIdx.x * SCAN_B + threadIdx.x;
    int lane = threadIdx.x & 31, wid = threadIdx.x >> 5;
    int v = (gid < n) ? deg[gid] : 0;
    int s = v;
    #pragma unroll
    for (int o = 1; o < 32; o <<= 1) {
        int t = __shfl_up_sync(0xffffffffu, s, o);
        if (lane >= o) s += t;
    }
    if (lane == 31) wsum[wid] = s;
    __syncthreads();
    if (wid == 0) {
        int ws = wsum[lane];
        #pragma unroll
        for (int o = 1; o < 32; o <<= 1) {
            int t = __shfl_up_sync(0xffffffffu, ws, o);
            if (lane >= o) ws += t;
        }
        wsum[lane] = ws;
    }
    __syncthreads();
    int base = wid ? wsum[wid - 1] : 0;
    int incl = base + s;
    if (gid < n) offs[gid] = incl - v;
    if (threadIdx.x == SCAN_B - 1) blksum[blockIdx.x] = incl;
}
__global__ void k_scan_blk(const int* __restrict__ blksum, int* __restrict__ blkoff,
                           int* __restrict__ offs, int nblk, int n) {
    __shared__ int sm[64];
    int t = threadIdx.x;
    int v = (t < nblk) ? blksum[t] : 0;
    sm[t] = v;
    __syncthreads();
    #pragma unroll
    for (int d = 1; d < 64; d <<= 1) {
        int tv = (t >= d) ? sm[t - d] : 0;
        __syncthreads();
        sm[t] += tv;
        __syncthreads();
    }
    if (t < nblk) blkoff[t] = sm[t] - v;
    if (t == 63) offs[n] = sm[63];
}
__global__ void k_scan_add(int* __restrict__ offs, const int* __restrict__ blkoff,
                           int* __restrict__ cursor, int n) {
    int gid = blockIdx.x * SCAN_B + threadIdx.x;
    if (gid < n) {
        int o = offs[gid] + blkoff[blockIdx.x];
        offs[gid] = o;
        cursor[gid] = o;
    }
}
__global__ void k_fill_csr(const int* __restrict__ src, const int* __restrict__ dst,
                           int* __restrict__ cursor, int* __restrict__ csr, int e) {
    int i = blockIdx.x * blockDim.x + threadIdx.x;
    if (i < e) {
        int p = atomicAdd(&cursor[dst[i]], 1);
        csr[p] = src[i];
    }
}

// ---------------- GEMM v5 (R10 exact): fp16 mma, full-K cp.async pipeline ----------------
#define STAGE_B 18432
#define G5_SMEM (4 * STAGE_B)
#define CPWAIT(n) asm volatile("cp.async.wait_group " #n ";")

template <int KT, int MODE>
__global__ __launch_bounds__(128, 2) void k_gemm5(
    const __half* __restrict__ A, const uint32_t* __restrict__ img,
    const float* __restrict__ bias, float* __restrict__ C, __half* __restrict__ Ch,
    int M, int Ns, int relu) {
    extern __shared__ uint32_t sm[];
    constexpr int NK = KT / 32;
    int tid = threadIdx.x;
    int wid = tid >> 5, lane = tid & 31;
    int grp = lane >> 2, lig = lane & 3;
    const int wm = (wid & 1) * 64;
    const int wg8 = (wid >> 1) * 8;
    const int bm = blockIdx.x * 128, bn = blockIdx.y * 128;
    const uint32_t* imgB = img + (size_t)blockIdx.y * NK * 2048;
    uint32_t sbase = smem_u32(sm);

    float acc[4][8][4];
    #pragma unroll
    for (int i = 0; i < 4; i++)
        #pragma unroll
        for (int j = 0; j < 8; j++)
            #pragma unroll
            for (int q = 0; q < 4; q++) acc[i][j][q] = 0.f;

    auto stage = [&](int kc) {
        uint32_t abase = sbase + kc * STAGE_B;
        #pragma unroll
        for (int i = 0; i < 8; i++) {
            int idx = tid + i * 128;
            int r = idx >> 3, s = idx & 7;
            int gr = bm + r;
            uint32_t dst = abase + (uint32_t)(r * 80 + s * 8);
            const __half* src = A + (size_t)gr * KT + kc * 32 + s * 4;
            int sz = (gr < M) ? 8 : 0;
            asm volatile("cp.async.ca.shared.global [%0], [%1], 8, %2;"
                         :: "r"(dst), "l"(src), "r"(sz));
        }
        uint32_t bbase = abase + 2560 * 4;
        const uint32_t* bsrc = imgB + kc * 2048;
        #pragma unroll
        for (int i = 0; i < 4; i++) {
            int idx = tid + i * 128;
            uint32_t dst = bbase + (uint32_t)idx * 16;
            asm volatile("cp.async.ca.shared.global [%0], [%1], 16, 16;"
                         :: "r"(dst), "l"(bsrc + idx * 4));
        }
        asm volatile("cp.async.commit_group;");
    };

    #pragma unroll
    for (int kc = 0; kc < NK; kc++) stage(kc);

    auto compute = [&](int kc) {
        const uint32_t* As = sm + kc * 4608;
        const uint32_t* Bs = As + 2560;
        uint4 bq[8];
        #pragma unroll
        for (int nt = 0; nt < 8; nt++)
            bq[nt] = *(const uint4*)(Bs + ((wg8 + nt) * 32 + lane) * 4);
        #pragma unroll
        for (int k16 = 0; k16 < 2; k16++) {
            #pragma unroll
            for (int mt = 0; mt < 4; mt++) {
                int rw = (wm + mt * 16 + grp) * 20 + k16 * 8 + lig;
                uint32_t av[4];
                av[0] = As[rw];
                av[1] = As[rw + 160];
                av[2] = As[rw + 4];
                av[3] = As[rw + 164];
                #pragma unroll
                for (int nt = 0; nt < 8; nt++) {
                    uint32_t bv[2];
                    if (k16 == 0) { bv[0] = bq[nt].x; bv[1] = bq[nt].y; }
                    else          { bv[0] = bq[nt].z; bv[1] = bq[nt].w; }
                    mma_f16(acc[mt][nt], av, bv);
                }
            }
        }
    };

    if (NK == 4) {
        CPWAIT(3); __syncthreads(); compute(0);
        CPWAIT(2); __syncthreads(); compute(1);
        CPWAIT(1); __syncthreads(); compute(2);
        CPWAIT(0); __syncthreads(); compute(3);
    } else {
        CPWAIT(1); __syncthreads(); compute(0);
        CPWAIT(0); __syncthreads(); compute(1);
    }

    #pragma unroll
    for (int mt = 0; mt < 4; mt++) {
        #pragma unroll
        for (int nt = 0; nt < 8; nt++) {
            int col = bn + (wg8 + nt) * 8 + lig * 2;
            float b0 = __ldg(bias + col), b1 = __ldg(bias + col + 1);
            int row0 = bm + wm + mt * 16 + grp;
            int row1 = row0 + 8;
            float v0 = acc[mt][nt][0] + b0;
            float v1 = acc[mt][nt][1] + b1;
            float v2 = acc[mt][nt][2] + b0;
            float v3 = acc[mt][nt][3] + b1;
            if (relu) {
                v0 = fmaxf(v0, 0.f); v1 = fmaxf(v1, 0.f);
                v2 = fmaxf(v2, 0.f); v3 = fmaxf(v3, 0.f);
            }
            if (MODE == 0) {
                if (row0 < M) {
                    *(float2*)(C + (size_t)row0 * Ns + col) = make_float2(v0, v1);
                    if (Ch) *(__half2*)(Ch + (size_t)row0 * Ns + col) = __floats2half2_rn(v0, v1);
                }
                if (row1 < M) {
                    *(float2*)(C + (size_t)row1 * Ns + col) = make_float2(v2, v3);
                    if (Ch) *(__half2*)(Ch + (size_t)row1 * Ns + col) = __floats2half2_rn(v2, v3);
                }
            } else {
                if (row0 < M) *(__half2*)(Ch + (size_t)row0 * 1024 + col) = __floats2half2_rn(v0, v1);
                if (row1 < M) *(__half2*)(Ch + (size_t)row1 * 1024 + col) = __floats2half2_rn(v2, v3);
            }
        }
    }
}

// ---------------- fused predictor: z1=relu(h@W1+b1); z2=relu(z1@W2+b2); out=clip(z2@w3+b3) ----------------
__global__ __launch_bounds__(128, 2) void k_pred_fused(
    const __half* __restrict__ A, const uint32_t* __restrict__ img1,
    const uint32_t* __restrict__ img2,
    const float* __restrict__ b1, const float* __restrict__ b2,
    const float* __restrict__ w3, const float* __restrict__ b3,
    float* __restrict__ out, int M) {
    extern __shared__ uint32_t sm[];
    constexpr int NK = 4;
    int tid = threadIdx.x;
    int wid = tid >> 5, lane = tid & 31;
    int grp = lane >> 2, lig = lane & 3;
    const int wm = (wid & 1) * 64;
    const int wg8 = (wid >> 1) * 8;
    const int bm = blockIdx.x * 128;
    uint32_t sbase = smem_u32(sm);

    float acc[4][8][4];
    #pragma unroll
    for (int i = 0; i < 4; i++)
        #pragma unroll
        for (int j = 0; j < 8; j++)
            #pragma unroll
            for (int q = 0; q < 4; q++) acc[i][j][q] = 0.f;

    auto stageB = [&](int kc, const uint32_t* imgsrc) {
        uint32_t bbase = sbase + kc * STAGE_B + 2560 * 4;
        const uint32_t* bsrc = imgsrc + kc * 2048;
        #pragma unroll
        for (int i = 0; i < 4; i++) {
            int idx = tid + i * 128;
            uint32_t dst = bbase + (uint32_t)idx * 16;
            asm volatile("cp.async.ca.shared.global [%0], [%1], 16, 16;"
                         :: "r"(dst), "l"(bsrc + idx * 4));
        }
        asm volatile("cp.async.commit_group;");
    };
    auto stage1 = [&](int kc) {
        uint32_t abase = sbase + kc * STAGE_B;
        #pragma unroll
        for (int i = 0; i < 8; i++) {
            int idx = tid + i * 128;
            int r = idx >> 3, s = idx & 7;
            int gr = bm + r;
            uint32_t dst = abase + (uint32_t)(r * 80 + s * 8);
            const __half* src = A + (size_t)gr * HID + kc * 32 + s * 4;
            int sz = (gr < M) ? 8 : 0;
            asm volatile("cp.async.ca.shared.global [%0], [%1], 8, %2;"
                         :: "r"(dst), "l"(src), "r"(sz));
        }
        uint32_t bbase = abase + 2560 * 4;
        const uint32_t* bsrc = img1 + kc * 2048;
        #pragma unroll
        for (int i = 0; i < 4; i++) {
            int idx = tid + i * 128;
            uint32_t dst = bbase + (uint32_t)idx * 16;
            asm volatile("cp.async.ca.shared.global [%0], [%1], 16, 16;"
                         :: "r"(dst), "l"(bsrc + idx * 4));
        }
        asm volatile("cp.async.commit_group;");
    };

    auto compute = [&](int kc) {
        const uint32_t* As = sm + kc * 4608;
        const uint32_t* Bs = As + 2560;
        uint4 bq[8];
        #pragma unroll
        for (int nt = 0; nt < 8; nt++)
            bq[nt] = *(const uint4*)(Bs + ((wg8 + nt) * 32 + lane) * 4);
        #pragma unroll
        for (int k16 = 0; k16 < 2; k16++) {
            #pragma unroll
            for (int mt = 0; mt < 4; mt++) {
                int rw = (wm + mt * 16 + grp) * 20 + k16 * 8 + lig;
                uint32_t av[4];
                av[0] = As[rw];
                av[1] = As[rw + 160];
                av[2] = As[rw + 4];
                av[3] = As[rw + 164];
                #pragma unroll
                for (int nt = 0; nt < 8; nt++) {
                    uint32_t bv[2];
                    if (k16 == 0) { bv[0] = bq[nt].x; bv[1] = bq[nt].y; }
                    else          { bv[0] = bq[nt].z; bv[1] = bq[nt].w; }
                    mma_f16(acc[mt][nt], av, bv);
                }
            }
        }
    };

    // pass 1: z1 = relu(A @ W1 + b1)
    #pragma unroll
    for (int kc = 0; kc < NK; kc++) stage1(kc);
    CPWAIT(3); __syncthreads(); compute(0);
    CPWAIT(2); __syncthreads(); compute(1);
    CPWAIT(1); __syncthreads(); compute(2);
    CPWAIT(0); __syncthreads(); compute(3);
    __syncthreads();   // all warps done reading stage buffers

    // write z1 fp16 into A-slots (block-local rows), reload B-slots with W2 image
    #pragma unroll
    for (int mt = 0; mt < 4; mt++) {
        #pragma unroll
        for (int nt = 0; nt < 8; nt++) {
            int col = (wg8 + nt) * 8 + lig * 2;
            float b0 = __ldg(b1 + col), bb = __ldg(b1 + col + 1);
            float v0 = fmaxf(acc[mt][nt][0] + b0, 0.f);
            float v1 = fmaxf(acc[mt][nt][1] + bb, 0.f);
            float v2 = fmaxf(acc[mt][nt][2] + b0, 0.f);
            float v3 = fmaxf(acc[mt][nt][3] + bb, 0.f);
            int row0 = wm + mt * 16 + grp;
            int kcid = col >> 5;
            int wofs = (col & 31) >> 1;
            uint32_t* As0 = sm + kcid * 4608;
            __half2 h01 = __floats2half2_rn(v0, v1);
            __half2 h23 = __floats2half2_rn(v2, v3);
            As0[row0 * 20 + wofs] = *(uint32_t*)&h01;
            As0[(row0 + 8) * 20 + wofs] = *(uint32_t*)&h23;
        }
    }
    #pragma unroll
    for (int kc = 0; kc < NK; kc++) stageB(kc, img2);
    CPWAIT(0);
    __syncthreads();

    // pass 2: z2 = relu(z1 @ W2 + b2); acc reset
    #pragma unroll
    for (int i = 0; i < 4; i++)
        #pragma unroll
        for (int j = 0; j < 8; j++)
            #pragma unroll
            for (int q = 0; q < 4; q++) acc[i][j][q] = 0.f;
    compute(0); compute(1); compute(2); compute(3);

    // p3 dot: cols 0..63 live in warps 0,1 (wg8 == 0), covering all 128 rows
    if (wid < 2) {
        #pragma unroll
        for (int mt = 0; mt < 4; mt++) {
            float s0 = 0.f, s1 = 0.f;
            #pragma unroll
            for (int nt = 0; nt < 8; nt++) {
                int col = nt * 8 + lig * 2;
                float w30 = __ldg(w3 + col), w31 = __ldg(w3 + col + 1);
                float bb0 = __ldg(b2 + col), bb1 = __ldg(b2 + col + 1);
                s0 += fmaxf(acc[mt][nt][0] + bb0, 0.f) * w30
                    + fmaxf(acc[mt][nt][1] + bb1, 0.f) * w31;
                s1 += fmaxf(acc[mt][nt][2] + bb0, 0.f) * w30
                    + fmaxf(acc[mt][nt][3] + bb1, 0.f) * w31;
            }
            s0 += __shfl_xor_sync(0xffffffffu, s0, 1);
            s0 += __shfl_xor_sync(0xffffffffu, s0, 2);
            s1 += __shfl_xor_sync(0xffffffffu, s1, 1);
            s1 += __shfl_xor_sync(0xffffffffu, s1, 2);
            if (lig == 0) {
                int row0 = bm + wm + mt * 16 + grp;
                float sc0 = fminf(fmaxf(s0 + b3[0], -15.f), 15.f);
                float sc1 = fminf(fmaxf(s1 + b3[0], -15.f), 15.f);
                if (row0 < M) out[row0] = sc0;
                if (row0 + 8 < M) out[row0 + 8] = sc1;
            }
        }
    }
}

// ---------------- GATv2 edge kernel (R10 exact) ----------------
__device__ __forceinline__ float h2dot(const __half2 a01, const __half2 a23,
                                       const __half2 xr01, const __half2 xr23,
                                       const __half2 neg2,
                                       const uint2 raw, float2* f01, float2* f23) {
    __half2 v01 = *(const __half2*)&raw.x, v23 = *(const __half2*)&raw.y;
    __half2 m01 = __hadd2(v01, xr01), m23 = __hadd2(v23, xr23);
    m01 = __hmax2(m01, __hmul2(m01, neg2));
    m23 = __hmax2(m23, __hmul2(m23, neg2));
    __half2 d2 = __hfma2(a23, m23, __hmul2(a01, m01));
    float2 df = __half22float2(d2);
    *f01 = __half22float2(v01);
    *f23 = __half22float2(v23);
    return df.x + df.y;
}

__global__ __launch_bounds__(256) void k_gat_edge(
    const __half* __restrict__ xlr, const float* __restrict__ att,
    const float* __restrict__ cbias,
    const float* __restrict__ hin, float* __restrict__ hout, __half* __restrict__ houth,
    const int* __restrict__ offs, const int* __restrict__ csr) {
    int half_ = threadIdx.x >> 7;
    int node = blockIdx.x * 2 + half_;
    int t128 = threadIdx.x & 127;
    int w = t128 >> 5, lane = threadIdx.x & 31;
    __shared__ float hacc[2][HEADS][HID];

    if (node < NN) {
        int beg = offs[node], end = offs[node + 1];
        const int off = w * HID + lane * 4;
        uint2 xrraw = *(const uint2*)(xlr + (size_t)node * 1024 + HOUT + off);
        const __half2 xr01 = *(const __half2*)&xrraw.x, xr23 = *(const __half2*)&xrraw.y;
        float4 a4 = *(const float4*)(att + w * HID + lane * 4);
        const __half2 a01 = __floats2half2_rn(a4.x, a4.y);
        const __half2 a23 = __floats2half2_rn(a4.z, a4.w);
        const __half2 neg2 = __float2half2_rn(NEG_SLOPE);

        float emax = -1e30f, denom = 0.f;
        float4 acc = make_float4(0.f, 0.f, 0.f, 0.f);
        int i = beg;
        for (; i + 3 < end; i += 4) {
            int s0 = __ldg(csr + i),     s1 = __ldg(csr + i + 1);
            int s2 = __ldg(csr + i + 2), s3 = __ldg(csr + i + 3);
            uint2 r0 = *(const uint2*)(xlr + (size_t)s0 * 1024 + off);
            uint2 r1 = *(const uint2*)(xlr + (size_t)s1 * 1024 + off);
            uint2 r2 = *(const uint2*)(xlr + (size_t)s2 * 1024 + off);
            uint2 r3 = *(const uint2*)(xlr + (size_t)s3 * 1024 + off);
            float2 v0a, v0b, v1a, v1b, v2a, v2b, v3a, v3b;
            float p0 = h2dot(a01, a23, xr01, xr23, neg2, r0, &v0a, &v0b);
            float p1 = h2dot(a01, a23, xr01, xr23, neg2, r1, &v1a, &v1b);
            float p2 = h2dot(a01, a23, xr01, xr23, neg2, r2, &v2a, &v2b);
            float p3 = h2dot(a01, a23, xr01, xr23, neg2, r3, &v3a, &v3b);
            #pragma unroll
            for (int o = 16; o; o >>= 1) {
                p0 += __shfl_xor_sync(0xffffffffu, p0, o);
                p1 += __shfl_xor_sync(0xffffffffu, p1, o);
                p2 += __shfl_xor_sync(0xffffffffu, p2, o);
                p3 += __shfl_xor_sync(0xffffffffu, p3, o);
            }
            float nm = fmaxf(fmaxf(emax, fmaxf(p0, p1)), fmaxf(p2, p3));
            float sc = __expf(emax - nm);
            denom *= sc;
            acc.x *= sc; acc.y *= sc; acc.z *= sc; acc.w *= sc;
            emax = nm;
            float w0 = __expf(p0 - nm), w1 = __expf(p1 - nm);
            float w2 = __expf(p2 - nm), w3 = __expf(p3 - nm);
            denom += (w0 + w1) + (w2 + w3);
            acc.x += w0 * v0a.x + w1 * v1a.x + w2 * v2a.x + w3 * v3a.x;
            acc.y += w0 * v0a.y + w1 * v1a.y + w2 * v2a.y + w3 * v3a.y;
            acc.z += w0 * v0b.x + w1 * v1b.x + w2 * v2b.x + w3 * v3b.x;
            acc.w += w0 * v0b.y + w1 * v1b.y + w2 * v2b.y + w3 * v3b.y;
        }
        for (; i < end; i++) {
            int s0 = __ldg(csr + i);
            uint2 r0 = *(const uint2*)(xlr + (size_t)s0 * 1024 + off);
            float2 v0a, v0b;
            float p0 = h2dot(a01, a23, xr01, xr23, neg2, r0, &v0a, &v0b);
            #pragma unroll
            for (int o = 16; o; o >>= 1) p0 += __shfl_xor_sync(0xffffffffu, p0, o);
            float nm = fmaxf(emax, p0);
            float sc = __expf(emax - nm);
            denom *= sc;
            acc.x *= sc; acc.y *= sc; acc.z *= sc; acc.w *= sc;
            emax = nm;
            float w0 = __expf(p0 - nm);
            denom += w0;
            acc.x += w0 * v0a.x; acc.y += w0 * v0a.y;
            acc.z += w0 * v0b.x; acc.w += w0 * v0b.y;
        }
        float inv = denom > 0.f ? 1.f / denom : 0.f;
        hacc[half_][w][lane * 4 + 0] = acc.x * inv;
        hacc[half_][w][lane * 4 + 1] = acc.y * inv;
        hacc[half_][w][lane * 4 + 2] = acc.z * inv;
        hacc[half_][w][lane * 4 + 3] = acc.w * inv;
    }
    __syncthreads();
    if (node < NN) {
        float sv = (hacc[half_][0][t128] + hacc[half_][1][t128] +
                    hacc[half_][2][t128] + hacc[half_][3][t128]) * 0.25f
                 + cbias[t128] + hin[(size_t)node * HID + t128];
        sv = fmaxf(sv, 0.f);
        hout[(size_t)node * HID + t128] = sv;
        houth[(size_t)node * HID + t128] = __float2half(sv);
    }
}

// ---------------- launch ----------------
extern "C" void kernel_launch(void* const* d_in, const int* in_sizes, int n_in,
                              void* d_out, int out_size) {
    const float* x      = (const float*)d_in[0];
    const int*   eidx   = (const int*)d_in[1];
    const float* emb_W  = (const float*)d_in[3];
    const float* emb_b  = (const float*)d_in[4];
    const float* Wl     = (const float*)d_in[5];
    const float* bl     = (const float*)d_in[6];
    const float* Wr     = (const float*)d_in[7];
    const float* br     = (const float*)d_in[8];
    const float* att    = (const float*)d_in[9];
    const float* cbias  = (const float*)d_in[10];
    const float* p1_W   = (const float*)d_in[11];
    const float* p1_b   = (const float*)d_in[12];
    const float* p2_W   = (const float*)d_in[13];
    const float* p2_b   = (const float*)d_in[14];
    const float* p3_W   = (const float*)d_in[15];
    const float* p3_b   = (const float*)d_in[16];
    float* out = (float*)d_out;

    const int* srcp = eidx;
    const int* dstp = eidx + EE;

    float *hA, *hB, *bB, *p2b;
    __half *hAh, *hBh, *xh, *xlrh;
    uint32_t* img;
    int *deg, *offs, *cursor, *csr, *blksum, *blkoff;
    cudaGetSymbolAddress((void**)&hA, g_hA);
    cudaGetSymbolAddress((void**)&hB, g_hB);
    cudaGetSymbolAddress((void**)&hAh, g_hAh);
    cudaGetSymbolAddress((void**)&hBh, g_hBh);
    cudaGetSymbolAddress((void**)&xh, g_xh);
    cudaGetSymbolAddress((void**)&xlrh, g_xlrh);
    cudaGetSymbolAddress((void**)&img, g_img);
    cudaGetSymbolAddress((void**)&bB, g_bB);
    cudaGetSymbolAddress((void**)&p2b, g_p2b);
    cudaGetSymbolAddress((void**)&deg, g_deg);
    cudaGetSymbolAddress((void**)&offs, g_offs);
    cudaGetSymbolAddress((void**)&cursor, g_cursor);
    cudaGetSymbolAddress((void**)&csr, g_csr);
    cudaGetSymbolAddress((void**)&blksum, g_blksum);
    cudaGetSymbolAddress((void**)&blkoff, g_blkoff);

    cudaFuncSetAttribute(k_gemm5<64, 0>,  cudaFuncAttributeMaxDynamicSharedMemorySize, G5_SMEM);
    cudaFuncSetAttribute(k_gemm5<128, 0>, cudaFuncAttributeMaxDynamicSharedMemorySize, G5_SMEM);
    cudaFuncSetAttribute(k_gemm5<128, 1>, cudaFuncAttributeMaxDynamicSharedMemorySize, G5_SMEM);
    cudaFuncSetAttribute(k_pred_fused,    cudaFuncAttributeMaxDynamicSharedMemorySize, G5_SMEM);

    const int MB = (NN + 127) / 128;  // 391

    // ---- fork a side stream: x->fp16 then CSR build ----
    cudaStream_t s2;
    cudaStreamCreateWithFlags(&s2, cudaStreamNonBlocking);
    cudaEvent_t evFork, evH2, evJoin;
    cudaEventCreateWithFlags(&evFork, cudaEventDisableTiming);
    cudaEventCreateWithFlags(&evH2, cudaEventDisableTiming);
    cudaEventCreateWithFlags(&evJoin, cudaEventDisableTiming);

    cudaEventRecord(evFork, 0);
    cudaStreamWaitEvent(s2, evFork, 0);

    k_h2<<<(NN * FIN + 255) / 256, 256, 0, s2>>>(x, xh, NN * FIN);
    cudaEventRecord(evH2, s2);
    k_zero_int<<<(NN + 255) / 256, 256, 0, s2>>>(deg, NN);
    k_count_deg<<<(EE + 255) / 256, 256, 0, s2>>>(dstp, deg, EE);
    k_scan_part<<<NBLK, SCAN_B, 0, s2>>>(deg, offs, blksum, NN);
    k_scan_blk<<<1, 64, 0, s2>>>(blksum, blkoff, offs, NBLK, NN);
    k_scan_add<<<NBLK, SCAN_B, 0, s2>>>(offs, blkoff, cursor, NN);
    k_fill_csr<<<(EE + 255) / 256, 256, 0, s2>>>(srcp, dstp, cursor, csr, EE);
    cudaEventRecord(evJoin, s2);

    // main stream: prep + embedding + layer-1 GEMM
    k_img<<<(IMG_TOTAL + 255) / 256, 256>>>(emb_W, Wl, Wr, p1_W, p2_W, bl, br, p2_b,
                                            img, bB, p2b);
    cudaStreamWaitEvent(0, evH2, 0);
    k_gemm5<64, 0><<<dim3(MB, 1), 128, 2 * STAGE_B>>>(xh, img + IMG_EMB, emb_b, hA, hAh, NN, HID, 1);
    k_gemm5<128, 1><<<dim3(MB, 8), 128, 4 * STAGE_B>>>(hAh, img + IMG_WB, bB, nullptr, xlrh, NN, 1024, 0);

    // join: edge kernel needs both xlr (main) and csr (side)
    cudaStreamWaitEvent(0, evJoin, 0);

    // layer 1 edge
    float* hc = hA;   __half* hch = hAh;
    float* hn = hB;   __half* hnh = hBh;
    k_gat_edge<<<(NN + 1) / 2, 256>>>(xlrh, att, cbias, hc, hn, hnh, offs, csr);
    { float* t = hc; hc = hn; hn = t; __half* th = hch; hch = hnh; hnh = th; }

    // layers 2..3
    for (int l = 1; l < LAYERS; l++) {
        k_gemm5<128, 1><<<dim3(MB, 8), 128, 4 * STAGE_B>>>(
            hch, img + IMG_WB + (size_t)l * 65536, bB + (size_t)l * 1024, nullptr, xlrh, NN, 1024, 0);
        k_gat_edge<<<(NN + 1) / 2, 256>>>(xlrh, att + (size_t)l * HEADS * HID,
                                          cbias + l * HID, hc, hn, hnh, offs, csr);
        float* t = hc; hc = hn; hn = t; __half* th = hch; hch = hnh; hnh = th;
    }

    // fused predictor: p1 -> p2 -> p3 in one kernel
    k_pred_fused<<<MB, 128, G5_SMEM>>>(hch, img + IMG_P1, img + IMG_P2,
                                       p1_b, p2b, p3_W, p3_b, out, NN);

    cudaEventDestroy(evFork);
    cudaEventDestroy(evH2);
    cudaEventDestroy(evJoin);
    cudaStreamDestroy(s2);
}

// round 17
// speedup vs baseline: 1.5078x; 1.2092x over previous
#include <cuda_runtime.h>
#include <cuda_fp16.h>
#include <math.h>
#include <stdint.h>

#define NN   50000
#define EE   800000
#define FIN  64
#define HID  128
#define HEADS 4
#define HOUT 512
#define LAYERS 3
#define NEG_SLOPE 0.2f
#define SCAN_B 1024
#define NBLK ((NN + SCAN_B - 1) / SCAN_B)

#define IMG_EMB 0
#define IMG_WB  4096
#define IMG_P1  (4096 + 3 * 65536)
#define IMG_P2  (IMG_P1 + 8192)
#define IMG_TOTAL (IMG_P2 + 8192)

// ---------------- scratch ----------------
__device__ float    g_hA[(size_t)NN * HID];
__device__ float    g_hB[(size_t)NN * HID];
__device__ __half   g_hAh[(size_t)NN * HID];
__device__ __half   g_hBh[(size_t)NN * HID];
__device__ __half   g_xh[(size_t)NN * FIN];
__device__ __half   g_xlrh[(size_t)NN * 1024];
__device__ uint32_t g_img[IMG_TOTAL];
__device__ float    g_bB[(size_t)LAYERS * 1024];
__device__ float    g_p2b[128];
__device__ int      g_deg[NN];
__device__ int      g_offs[NN + 1];
__device__ int      g_cursor[NN];
__device__ int      g_csr[EE];
__device__ int      g_blksum[NBLK];
__device__ int      g_blkoff[NBLK];

__device__ __forceinline__ void mma_f16(float* d, const uint32_t* a, const uint32_t* b) {
    asm volatile(
        "mma.sync.aligned.m16n8k16.row.col.f32.f16.f16.f32 "
        "{%0,%1,%2,%3}, {%4,%5,%6,%7}, {%8,%9}, {%0,%1,%2,%3};"
        : "+f"(d[0]), "+f"(d[1]), "+f"(d[2]), "+f"(d[3])
        : "r"(a[0]), "r"(a[1]), "r"(a[2]), "r"(a[3]), "r"(b[0]), "r"(b[1]));
}
__device__ __forceinline__ uint32_t smem_u32(const void* p) {
    uint32_t a;
    asm("{ .reg .u64 t; cvta.to.shared.u64 t, %1; cvt.u32.u64 %0, t; }" : "=r"(a) : "l"(p));
    return a;
}

// ---------------- prep: fp16 B fragment images + bias packing ----------------
__global__ void k_img(const float* __restrict__ emb_W, const float* __restrict__ Wl,
                      const float* __restrict__ Wr, const float* __restrict__ p1_W,
                      const float* __restrict__ p2_W,
                      const float* __restrict__ bl, const float* __restrict__ br,
                      const float* __restrict__ p2_b,
                      uint32_t* __restrict__ img, float* __restrict__ bB,
                      float* __restrict__ p2bp) {
    int w = blockIdx.x * blockDim.x + threadIdx.x;
    if (w >= IMG_TOTAL) return;
    if (w < LAYERS * 1024) {
        int l = w / 1024, n = w % 1024;
        bB[w] = (n < HOUT) ? bl[l * HOUT + n] : br[l * HOUT + n - HOUT];
    }
    if (w < 128) p2bp[w] = (w < 64) ? p2_b[w] : 0.f;

    int rem, nc, seg;
    if (w < IMG_WB)      { seg = 0; rem = w;           nc = 2; }
    else if (w < IMG_P1) { seg = 1; rem = w - IMG_WB;  nc = 4; }
    else if (w < IMG_P2) { seg = 2; rem = w - IMG_P1;  nc = 4; }
    else                 { seg = 3; rem = w - IMG_P2;  nc = 4; }
    int layer = 0;
    if (seg == 1) { layer = rem / 65536; rem %= 65536; }
    int cw = nc * 2048;
    int blk = rem / cw;
    int r2 = rem % cw;
    int kc = r2 / 2048;
    int u = r2 % 2048;
    int comp = u & 3;
    int lane = (u >> 2) & 31;
    int g = u >> 7;
    int lig = lane & 3, grp = lane >> 2;
    int k16 = comp >> 1, pairsel = comp & 1;
    int k = kc * 32 + k16 * 16 + pairsel * 8 + lig * 2;
    int n = blk * 128 + g * 8 + grp;
    float lo, hi;
    if (seg == 0) {
        lo = emb_W[k * HID + n];
        hi = emb_W[(k + 1) * HID + n];
    } else if (seg == 1) {
        if (n < HOUT) {
            lo = Wl[((size_t)layer * HID + k) * HOUT + n];
            hi = Wl[((size_t)layer * HID + k + 1) * HOUT + n];
        } else {
            lo = Wr[((size_t)layer * HID + k) * HOUT + (n - HOUT)];
            hi = Wr[((size_t)layer * HID + k + 1) * HOUT + (n - HOUT)];
        }
    } else if (seg == 2) {
        lo = p1_W[k * HID + n];
        hi = p1_W[(k + 1) * HID + n];
    } else {
        lo = (n < 64) ? p2_W[k * 64 + n] : 0.f;
        hi = (n < 64) ? p2_W[(k + 1) * 64 + n] : 0.f;
    }
    __half2 h2 = __floats2half2_rn(lo, hi);
    img[w] = *(uint32_t*)&h2;
}

__global__ void k_h2(const float* __restrict__ x, __half* __restrict__ xh, int n) {
    int i = blockIdx.x * blockDim.x + threadIdx.x;
    if (i < n) xh[i] = __float2half(x[i]);
}

// ---------------- CSR build ----------------
__global__ void k_zero_int(int* p, int n) {
    int i = blockIdx.x * blockDim.x + threadIdx.x;
    if (i < n) p[i] = 0;
}
__global__ void k_count_deg(const int* __restrict__ dst, int* __restrict__ deg, int e) {
    int i = blockIdx.x * blockDim.x + threadIdx.x;
    if (i < e) atomicAdd(&deg[dst[i]], 1);
}
__global__ void k_scan_part(const int* __restrict__ deg, int* __restrict__ offs,
                            int* __restrict__ blksum, int n) {
    __shared__ int wsum[32];
    int gid = blockIdx.x * SCAN_B + threadIdx.x;
    int lane = threadIdx.x & 31, wid = threadIdx.x >> 5;
    int v = (gid < n) ? deg[gid] : 0;
    int s = v;
    #pragma unroll
    for (int o = 1; o < 32; o <<= 1) {
        int t = __shfl_up_sync(0xffffffffu, s, o);
        if (lane >= o) s += t;
    }
    if (lane == 31) wsum[wid] = s;
    __syncthreads();
    if (wid == 0) {
        int ws = wsum[lane];
        #pragma unroll
        for (int o = 1; o < 32; o <<= 1) {
            int t = __shfl_up_sync(0xffffffffu, ws, o);
            if (lane >= o) ws += t;
        }
        wsum[lane] = ws;
    }
    __syncthreads();
    int base = wid ? wsum[wid - 1] : 0;
    int incl = base + s;
    if (gid < n) offs[gid] = incl - v;
    if (threadIdx.x == SCAN_B - 1) blksum[blockIdx.x] = incl;
}
__global__ void k_scan_blk(const int* __restrict__ blksum, int* __restrict__ blkoff,
                           int* __restrict__ offs, int nblk, int n) {
    __shared__ int sm[64];
    int t = threadIdx.x;
    int v = (t < nblk) ? blksum[t] : 0;
    sm[t] = v;
    __syncthreads();
    #pragma unroll
    for (int d = 1; d < 64; d <<= 1) {
        int tv = (t >= d) ? sm[t - d] : 0;
        __syncthreads();
        sm[t] += tv;
        __syncthreads();
    }
    if (t < nblk) blkoff[t] = sm[t] - v;
    if (t == 63) offs[n] = sm[63];
}
__global__ void k_scan_add(int* __restrict__ offs, const int* __restrict__ blkoff,
                           int* __restrict__ cursor, int n) {
    int gid = blockIdx.x * SCAN_B + threadIdx.x;
    if (gid < n) {
        int o = offs[gid] + blkoff[blockIdx.x];
        offs[gid] = o;
        cursor[gid] = o;
    }
}
__global__ void k_fill_csr(const int* __restrict__ src, const int* __restrict__ dst,
                           int* __restrict__ cursor, int* __restrict__ csr, int e) {
    int i = blockIdx.x * blockDim.x + threadIdx.x;
    if (i < e) {
        int p = atomicAdd(&cursor[dst[i]], 1);
        csr[p] = src[i];
    }
}

// ---------------- GEMM v5 (R10 exact): fp16 mma, full-K cp.async pipeline ----------------
#define STAGE_B 18432
#define G5_SMEM (4 * STAGE_B)
#define CPWAIT(n) asm volatile("cp.async.wait_group " #n ";")

template <int KT, int MODE>
__global__ __launch_bounds__(128, 2) void k_gemm5(
    const __half* __restrict__ A, const uint32_t* __restrict__ img,
    const float* __restrict__ bias, float* __restrict__ C, __half* __restrict__ Ch,
    int M, int Ns, int relu) {
    extern __shared__ uint32_t sm[];
    constexpr int NK = KT / 32;
    int tid = threadIdx.x;
    int wid = tid >> 5, lane = tid & 31;
    int grp = lane >> 2, lig = lane & 3;
    const int wm = (wid & 1) * 64;
    const int wg8 = (wid >> 1) * 8;
    const int bm = blockIdx.x * 128, bn = blockIdx.y * 128;
    const uint32_t* imgB = img + (size_t)blockIdx.y * NK * 2048;
    uint32_t sbase = smem_u32(sm);

    float acc[4][8][4];
    #pragma unroll
    for (int i = 0; i < 4; i++)
        #pragma unroll
        for (int j = 0; j < 8; j++)
            #pragma unroll
            for (int q = 0; q < 4; q++) acc[i][j][q] = 0.f;

    auto stage = [&](int kc) {
        uint32_t abase = sbase + kc * STAGE_B;
        #pragma unroll
        for (int i = 0; i < 8; i++) {
            int idx = tid + i * 128;
            int r = idx >> 3, s = idx & 7;
            int gr = bm + r;
            uint32_t dst = abase + (uint32_t)(r * 80 + s * 8);
            const __half* src = A + (size_t)gr * KT + kc * 32 + s * 4;
            int sz = (gr < M) ? 8 : 0;
            asm volatile("cp.async.ca.shared.global [%0], [%1], 8, %2;"
                         :: "r"(dst), "l"(src), "r"(sz));
        }
        uint32_t bbase = abase + 2560 * 4;
        const uint32_t* bsrc = imgB + kc * 2048;
        #pragma unroll
        for (int i = 0; i < 4; i++) {
            int idx = tid + i * 128;
            uint32_t dst = bbase + (uint32_t)idx * 16;
            asm volatile("cp.async.ca.shared.global [%0], [%1], 16, 16;"
                         :: "r"(dst), "l"(bsrc + idx * 4));
        }
        asm volatile("cp.async.commit_group;");
    };

    #pragma unroll
    for (int kc = 0; kc < NK; kc++) stage(kc);

    auto compute = [&](int kc) {
        const uint32_t* As = sm + kc * 4608;
        const uint32_t* Bs = As + 2560;
        uint4 bq[8];
        #pragma unroll
        for (int nt = 0; nt < 8; nt++)
            bq[nt] = *(const uint4*)(Bs + ((wg8 + nt) * 32 + lane) * 4);
        #pragma unroll
        for (int k16 = 0; k16 < 2; k16++) {
            #pragma unroll
            for (int mt = 0; mt < 4; mt++) {
                int rw = (wm + mt * 16 + grp) * 20 + k16 * 8 + lig;
                uint32_t av[4];
                av[0] = As[rw];
                av[1] = As[rw + 160];
                av[2] = As[rw + 4];
                av[3] = As[rw + 164];
                #pragma unroll
                for (int nt = 0; nt < 8; nt++) {
                    uint32_t bv[2];
                    if (k16 == 0) { bv[0] = bq[nt].x; bv[1] = bq[nt].y; }
                    else          { bv[0] = bq[nt].z; bv[1] = bq[nt].w; }
                    mma_f16(acc[mt][nt], av, bv);
                }
            }
        }
    };

    if (NK == 4) {
        CPWAIT(3); __syncthreads(); compute(0);
        CPWAIT(2); __syncthreads(); compute(1);
        CPWAIT(1); __syncthreads(); compute(2);
        CPWAIT(0); __syncthreads(); compute(3);
    } else {
        CPWAIT(1); __syncthreads(); compute(0);
        CPWAIT(0); __syncthreads(); compute(1);
    }

    #pragma unroll
    for (int mt = 0; mt < 4; mt++) {
        #pragma unroll
        for (int nt = 0; nt < 8; nt++) {
            int col = bn + (wg8 + nt) * 8 + lig * 2;
            float b0 = __ldg(bias + col), b1 = __ldg(bias + col + 1);
            int row0 = bm + wm + mt * 16 + grp;
            int row1 = row0 + 8;
            float v0 = acc[mt][nt][0] + b0;
            float v1 = acc[mt][nt][1] + b1;
            float v2 = acc[mt][nt][2] + b0;
            float v3 = acc[mt][nt][3] + b1;
            if (relu) {
                v0 = fmaxf(v0, 0.f); v1 = fmaxf(v1, 0.f);
                v2 = fmaxf(v2, 0.f); v3 = fmaxf(v3, 0.f);
            }
            if (MODE == 0) {
                if (row0 < M) {
                    *(float2*)(C + (size_t)row0 * Ns + col) = make_float2(v0, v1);
                    if (Ch) *(__half2*)(Ch + (size_t)row0 * Ns + col) = __floats2half2_rn(v0, v1);
                }
                if (row1 < M) {
                    *(float2*)(C + (size_t)row1 * Ns + col) = make_float2(v2, v3);
                    if (Ch) *(__half2*)(Ch + (size_t)row1 * Ns + col) = __floats2half2_rn(v2, v3);
                }
            } else {
                if (row0 < M) *(__half2*)(Ch + (size_t)row0 * 1024 + col) = __floats2half2_rn(v0, v1);
                if (row1 < M) *(__half2*)(Ch + (size_t)row1 * 1024 + col) = __floats2half2_rn(v2, v3);
            }
        }
    }
}

// ---------------- fused predictor (R16 exact) ----------------
__global__ __launch_bounds__(128, 2) void k_pred_fused(
    const __half* __restrict__ A, const uint32_t* __restrict__ img1,
    const uint32_t* __restrict__ img2,
    const float* __restrict__ b1, const float* __restrict__ b2,
    const float* __restrict__ w3, const float* __restrict__ b3,
    float* __restrict__ out, int M) {
    extern __shared__ uint32_t sm[];
    constexpr int NK = 4;
    int tid = threadIdx.x;
    int wid = tid >> 5, lane = tid & 31;
    int grp = lane >> 2, lig = lane & 3;
    const int wm = (wid & 1) * 64;
    const int wg8 = (wid >> 1) * 8;
    const int bm = blockIdx.x * 128;
    uint32_t sbase = smem_u32(sm);

    float acc[4][8][4];
    #pragma unroll
    for (int i = 0; i < 4; i++)
        #pragma unroll
        for (int j = 0; j < 8; j++)
            #pragma unroll
            for (int q = 0; q < 4; q++) acc[i][j][q] = 0.f;

    auto stageB = [&](int kc, const uint32_t* imgsrc) {
        uint32_t bbase = sbase + kc * STAGE_B + 2560 * 4;
        const uint32_t* bsrc = imgsrc + kc * 2048;
        #pragma unroll
        for (int i = 0; i < 4; i++) {
            int idx = tid + i * 128;
            uint32_t dst = bbase + (uint32_t)idx * 16;
            asm volatile("cp.async.ca.shared.global [%0], [%1], 16, 16;"
                         :: "r"(dst), "l"(bsrc + idx * 4));
        }
        asm volatile("cp.async.commit_group;");
    };
    auto stage1 = [&](int kc) {
        uint32_t abase = sbase + kc * STAGE_B;
        #pragma unroll
        for (int i = 0; i < 8; i++) {
            int idx = tid + i * 128;
            int r = idx >> 3, s = idx & 7;
            int gr = bm + r;
            uint32_t dst = abase + (uint32_t)(r * 80 + s * 8);
            const __half* src = A + (size_t)gr * HID + kc * 32 + s * 4;
            int sz = (gr < M) ? 8 : 0;
            asm volatile("cp.async.ca.shared.global [%0], [%1], 8, %2;"
                         :: "r"(dst), "l"(src), "r"(sz));
        }
        uint32_t bbase = abase + 2560 * 4;
        const uint32_t* bsrc = img1 + kc * 2048;
        #pragma unroll
        for (int i = 0; i < 4; i++) {
            int idx = tid + i * 128;
            uint32_t dst = bbase + (uint32_t)idx * 16;
            asm volatile("cp.async.ca.shared.global [%0], [%1], 16, 16;"
                         :: "r"(dst), "l"(bsrc + idx * 4));
        }
        asm volatile("cp.async.commit_group;");
    };

    auto compute = [&](int kc) {
        const uint32_t* As = sm + kc * 4608;
        const uint32_t* Bs = As + 2560;
        uint4 bq[8];
        #pragma unroll
        for (int nt = 0; nt < 8; nt++)
            bq[nt] = *(const uint4*)(Bs + ((wg8 + nt) * 32 + lane) * 4);
        #pragma unroll
        for (int k16 = 0; k16 < 2; k16++) {
            #pragma unroll
            for (int mt = 0; mt < 4; mt++) {
                int rw = (wm + mt * 16 + grp) * 20 + k16 * 8 + lig;
                uint32_t av[4];
                av[0] = As[rw];
                av[1] = As[rw + 160];
                av[2] = As[rw + 4];
                av[3] = As[rw + 164];
                #pragma unroll
                for (int nt = 0; nt < 8; nt++) {
                    uint32_t bv[2];
                    if (k16 == 0) { bv[0] = bq[nt].x; bv[1] = bq[nt].y; }
                    else          { bv[0] = bq[nt].z; bv[1] = bq[nt].w; }
                    mma_f16(acc[mt][nt], av, bv);
                }
            }
        }
    };

    #pragma unroll
    for (int kc = 0; kc < NK; kc++) stage1(kc);
    CPWAIT(3); __syncthreads(); compute(0);
    CPWAIT(2); __syncthreads(); compute(1);
    CPWAIT(1); __syncthreads(); compute(2);
    CPWAIT(0); __syncthreads(); compute(3);
    __syncthreads();

    #pragma unroll
    for (int mt = 0; mt < 4; mt++) {
        #pragma unroll
        for (int nt = 0; nt < 8; nt++) {
            int col = (wg8 + nt) * 8 + lig * 2;
            float b0 = __ldg(b1 + col), bb = __ldg(b1 + col + 1);
            float v0 = fmaxf(acc[mt][nt][0] + b0, 0.f);
            float v1 = fmaxf(acc[mt][nt][1] + bb, 0.f);
            float v2 = fmaxf(acc[mt][nt][2] + b0, 0.f);
            float v3 = fmaxf(acc[mt][nt][3] + bb, 0.f);
            int row0 = wm + mt * 16 + grp;
            int kcid = col >> 5;
            int wofs = (col & 31) >> 1;
            uint32_t* As0 = sm + kcid * 4608;
            __half2 h01 = __floats2half2_rn(v0, v1);
            __half2 h23 = __floats2half2_rn(v2, v3);
            As0[row0 * 20 + wofs] = *(uint32_t*)&h01;
            As0[(row0 + 8) * 20 + wofs] = *(uint32_t*)&h23;
        }
    }
    #pragma unroll
    for (int kc = 0; kc < NK; kc++) stageB(kc, img2);
    CPWAIT(0);
    __syncthreads();

    #pragma unroll
    for (int i = 0; i < 4; i++)
        #pragma unroll
        for (int j = 0; j < 8; j++)
            #pragma unroll
            for (int q = 0; q < 4; q++) acc[i][j][q] = 0.f;
    compute(0); compute(1); compute(2); compute(3);

    if (wid < 2) {
        #pragma unroll
        for (int mt = 0; mt < 4; mt++) {
            float s0 = 0.f, s1 = 0.f;
            #pragma unroll
            for (int nt = 0; nt < 8; nt++) {
                int col = nt * 8 + lig * 2;
                float w30 = __ldg(w3 + col), w31 = __ldg(w3 + col + 1);
                float bb0 = __ldg(b2 + col), bb1 = __ldg(b2 + col + 1);
                s0 += fmaxf(acc[mt][nt][0] + bb0, 0.f) * w30
                    + fmaxf(acc[mt][nt][1] + bb1, 0.f) * w31;
                s1 += fmaxf(acc[mt][nt][2] + bb0, 0.f) * w30
                    + fmaxf(acc[mt][nt][3] + bb1, 0.f) * w31;
            }
            s0 += __shfl_xor_sync(0xffffffffu, s0, 1);
            s0 += __shfl_xor_sync(0xffffffffu, s0, 2);
            s1 += __shfl_xor_sync(0xffffffffu, s1, 1);
            s1 += __shfl_xor_sync(0xffffffffu, s1, 2);
            if (lig == 0) {
                int row0 = bm + wm + mt * 16 + grp;
                float sc0 = fminf(fmaxf(s0 + b3[0], -15.f), 15.f);
                float sc1 = fminf(fmaxf(s1 + b3[0], -15.f), 15.f);
                if (row0 < M) out[row0] = sc0;
                if (row0 + 8 < M) out[row0 + 8] = sc1;
            }
        }
    }
}

// ---------------- GATv2 edge kernel v7: warp = 2 heads x 16 lanes, uint4 loads ----------------
__global__ __launch_bounds__(256) void k_gat_edge(
    const __half* __restrict__ xlr, const float* __restrict__ att,
    const float* __restrict__ cbias,
    const float* __restrict__ hin, float* __restrict__ hout, __half* __restrict__ houth,
    const int* __restrict__ offs, const int* __restrict__ csr) {
    int wid = threadIdx.x >> 5;
    int nl = wid >> 1;                  // node local 0..3
    int node = blockIdx.x * 4 + nl;
    int whalf = wid & 1;                // head pair
    int lane = threadIdx.x & 31;
    int gidx = lane >> 4;               // group within warp
    int head = whalf * 2 + gidx;
    int l16 = lane & 15;
    __shared__ float hacc[4][HEADS][HID];

    if (node < NN) {
        int beg = offs[node], end = offs[node + 1];
        const int off = head * HID + l16 * 8;   // 8 halves per lane
        uint4 xrr = *(const uint4*)(xlr + (size_t)node * 1024 + HOUT + off);
        const __half2 xq0 = *(const __half2*)&xrr.x, xq1 = *(const __half2*)&xrr.y;
        const __half2 xq2 = *(const __half2*)&xrr.z, xq3 = *(const __half2*)&xrr.w;
        float4 aa = *(const float4*)(att + head * HID + l16 * 8);
        float4 ab = *(const float4*)(att + head * HID + l16 * 8 + 4);
        const __half2 at0 = __floats2half2_rn(aa.x, aa.y);
        const __half2 at1 = __floats2half2_rn(aa.z, aa.w);
        const __half2 at2 = __floats2half2_rn(ab.x, ab.y);
        const __half2 at3 = __floats2half2_rn(ab.z, ab.w);
        const __half2 neg2 = __float2half2_rn(NEG_SLOPE);

        float emax = -1e30f, denom = 0.f;
        float acc[8];
        #pragma unroll
        for (int j = 0; j < 8; j++) acc[j] = 0.f;

        auto edot = [&](uint4 r, float* vf) -> float {
            __half2 v0 = *(__half2*)&r.x, v1 = *(__half2*)&r.y;
            __half2 v2 = *(__half2*)&r.z, v3 = *(__half2*)&r.w;
            __half2 m0 = __hadd2(v0, xq0), m1 = __hadd2(v1, xq1);
            __half2 m2 = __hadd2(v2, xq2), m3 = __hadd2(v3, xq3);
            m0 = __hmax2(m0, __hmul2(m0, neg2));
            m1 = __hmax2(m1, __hmul2(m1, neg2));
            m2 = __hmax2(m2, __hmul2(m2, neg2));
            m3 = __hmax2(m3, __hmul2(m3, neg2));
            __half2 d = __hmul2(at0, m0);
            d = __hfma2(at1, m1, d);
            d = __hfma2(at2, m2, d);
            d = __hfma2(at3, m3, d);
            float2 df = __half22float2(d);
            float2 f0 = __half22float2(v0), f1 = __half22float2(v1);
            float2 f2 = __half22float2(v2), f3 = __half22float2(v3);
            vf[0] = f0.x; vf[1] = f0.y; vf[2] = f1.x; vf[3] = f1.y;
            vf[4] = f2.x; vf[5] = f2.y; vf[6] = f3.x; vf[7] = f3.y;
            return df.x + df.y;
        };

        int i = beg;
        for (; i + 3 < end; i += 4) {
            int s0 = __ldg(csr + i),     s1 = __ldg(csr + i + 1);
            int s2 = __ldg(csr + i + 2), s3 = __ldg(csr + i + 3);
            uint4 r0 = *(const uint4*)(xlr + (size_t)s0 * 1024 + off);
            uint4 r1 = *(const uint4*)(xlr + (size_t)s1 * 1024 + off);
            uint4 r2 = *(const uint4*)(xlr + (size_t)s2 * 1024 + off);
            uint4 r3 = *(const uint4*)(xlr + (size_t)s3 * 1024 + off);
            float v0f[8], v1f[8], v2f[8], v3f[8];
            float p0 = edot(r0, v0f);
            float p1 = edot(r1, v1f);
            float p2 = edot(r2, v2f);
            float p3 = edot(r3, v3f);
            #pragma unroll
            for (int o = 8; o; o >>= 1) {      // in-group butterfly (16 lanes)
                p0 += __shfl_xor_sync(0xffffffffu, p0, o);
                p1 += __shfl_xor_sync(0xffffffffu, p1, o);
                p2 += __shfl_xor_sync(0xffffffffu, p2, o);
                p3 += __shfl_xor_sync(0xffffffffu, p3, o);
            }
            float nm = fmaxf(fmaxf(emax, fmaxf(p0, p1)), fmaxf(p2, p3));
            float sc = __expf(emax - nm);
            denom *= sc;
            #pragma unroll
            for (int j = 0; j < 8; j++) acc[j] *= sc;
            emax = nm;
            float w0 = __expf(p0 - nm), w1 = __expf(p1 - nm);
            float w2 = __expf(p2 - nm), w3 = __expf(p3 - nm);
            denom += (w0 + w1) + (w2 + w3);
            #pragma unroll
            for (int j = 0; j < 8; j++)
                acc[j] += w0 * v0f[j] + w1 * v1f[j] + w2 * v2f[j] + w3 * v3f[j];
        }
        for (; i < end; i++) {
            int s0 = __ldg(csr + i);
            uint4 r0 = *(const uint4*)(xlr + (size_t)s0 * 1024 + off);
            float v0f[8];
            float p0 = edot(r0, v0f);
            #pragma unroll
            for (int o = 8; o; o >>= 1) p0 += __shfl_xor_sync(0xffffffffu, p0, o);
            float nm = fmaxf(emax, p0);
            float sc = __expf(emax - nm);
            denom *= sc;
            #pragma unroll
            for (int j = 0; j < 8; j++) acc[j] *= sc;
            emax = nm;
            float w0 = __expf(p0 - nm);
            denom += w0;
            #pragma unroll
            for (int j = 0; j < 8; j++) acc[j] += w0 * v0f[j];
        }
        float inv = denom > 0.f ? 1.f / denom : 0.f;
        #pragma unroll
        for (int j = 0; j < 8; j++) hacc[nl][head][l16 * 8 + j] = acc[j] * inv;
    }
    __syncthreads();

    // epilogue: thread -> (node, 2 cols)
    int nl2 = threadIdx.x >> 6;
    int node2 = blockIdx.x * 4 + nl2;
    int c = (threadIdx.x & 63) * 2;
    if (node2 < NN) {
        float sv0 = (hacc[nl2][0][c] + hacc[nl2][1][c] + hacc[nl2][2][c] + hacc[nl2][3][c]) * 0.25f
                  + cbias[c] + hin[(size_t)node2 * HID + c];
        float sv1 = (hacc[nl2][0][c + 1] + hacc[nl2][1][c + 1] + hacc[nl2][2][c + 1] + hacc[nl2][3][c + 1]) * 0.25f
                  + cbias[c + 1] + hin[(size_t)node2 * HID + c + 1];
        sv0 = fmaxf(sv0, 0.f);
        sv1 = fmaxf(sv1, 0.f);
        *(float2*)(hout + (size_t)node2 * HID + c) = make_float2(sv0, sv1);
        *(__half2*)(houth + (size_t)node2 * HID + c) = __floats2half2_rn(sv0, sv1);
    }
}

// ---------------- launch ----------------
extern "C" void kernel_launch(void* const* d_in, const int* in_sizes, int n_in,
                              void* d_out, int out_size) {
    const float* x      = (const float*)d_in[0];
    const int*   eidx   = (const int*)d_in[1];
    const float* emb_W  = (const float*)d_in[3];
    const float* emb_b  = (const float*)d_in[4];
    const float* Wl     = (const float*)d_in[5];
    const float* bl     = (const float*)d_in[6];
    const float* Wr     = (const float*)d_in[7];
    const float* br     = (const float*)d_in[8];
    const float* att    = (const float*)d_in[9];
    const float* cbias  = (const float*)d_in[10];
    const float* p1_W   = (const float*)d_in[11];
    const float* p1_b   = (const float*)d_in[12];
    const float* p2_W   = (const float*)d_in[13];
    const float* p2_b   = (const float*)d_in[14];
    const float* p3_W   = (const float*)d_in[15];
    const float* p3_b   = (const float*)d_in[16];
    float* out = (float*)d_out;

    const int* srcp = eidx;
    const int* dstp = eidx + EE;

    float *hA, *hB, *bB, *p2b;
    __half *hAh, *hBh, *xh, *xlrh;
    uint32_t* img;
    int *deg, *offs, *cursor, *csr, *blksum, *blkoff;
    cudaGetSymbolAddress((void**)&hA, g_hA);
    cudaGetSymbolAddress((void**)&hB, g_hB);
    cudaGetSymbolAddress((void**)&hAh, g_hAh);
    cudaGetSymbolAddress((void**)&hBh, g_hBh);
    cudaGetSymbolAddress((void**)&xh, g_xh);
    cudaGetSymbolAddress((void**)&xlrh, g_xlrh);
    cudaGetSymbolAddress((void**)&img, g_img);
    cudaGetSymbolAddress((void**)&bB, g_bB);
    cudaGetSymbolAddress((void**)&p2b, g_p2b);
    cudaGetSymbolAddress((void**)&deg, g_deg);
    cudaGetSymbolAddress((void**)&offs, g_offs);
    cudaGetSymbolAddress((void**)&cursor, g_cursor);
    cudaGetSymbolAddress((void**)&csr, g_csr);
    cudaGetSymbolAddress((void**)&blksum, g_blksum);
    cudaGetSymbolAddress((void**)&blkoff, g_blkoff);

    cudaFuncSetAttribute(k_gemm5<64, 0>,  cudaFuncAttributeMaxDynamicSharedMemorySize, G5_SMEM);
    cudaFuncSetAttribute(k_gemm5<128, 0>, cudaFuncAttributeMaxDynamicSharedMemorySize, G5_SMEM);
    cudaFuncSetAttribute(k_gemm5<128, 1>, cudaFuncAttributeMaxDynamicSharedMemorySize, G5_SMEM);
    cudaFuncSetAttribute(k_pred_fused,    cudaFuncAttributeMaxDynamicSharedMemorySize, G5_SMEM);

    const int MB = (NN + 127) / 128;  // 391

    // ---- fork a side stream: x->fp16 then CSR build ----
    cudaStream_t s2;
    cudaStreamCreateWithFlags(&s2, cudaStreamNonBlocking);
    cudaEvent_t evFork, evH2, evJoin;
    cudaEventCreateWithFlags(&evFork, cudaEventDisableTiming);
    cudaEventCreateWithFlags(&evH2, cudaEventDisableTiming);
    cudaEventCreateWithFlags(&evJoin, cudaEventDisableTiming);

    cudaEventRecord(evFork, 0);
    cudaStreamWaitEvent(s2, evFork, 0);

    k_h2<<<(NN * FIN + 255) / 256, 256, 0, s2>>>(x, xh, NN * FIN);
    cudaEventRecord(evH2, s2);
    k_zero_int<<<(NN + 255) / 256, 256, 0, s2>>>(deg, NN);
    k_count_deg<<<(EE + 255) / 256, 256, 0, s2>>>(dstp, deg, EE);
    k_scan_part<<<NBLK, SCAN_B, 0, s2>>>(deg, offs, blksum, NN);
    k_scan_blk<<<1, 64, 0, s2>>>(blksum, blkoff, offs, NBLK, NN);
    k_scan_add<<<NBLK, SCAN_B, 0, s2>>>(offs, blkoff, cursor, NN);
    k_fill_csr<<<(EE + 255) / 256, 256, 0, s2>>>(srcp, dstp, cursor, csr, EE);
    cudaEventRecord(evJoin, s2);

    // main stream: prep + embedding + layer-1 GEMM
    k_img<<<(IMG_TOTAL + 255) / 256, 256>>>(emb_W, Wl, Wr, p1_W, p2_W, bl, br, p2_b,
                                            img, bB, p2b);
    cudaStreamWaitEvent(0, evH2, 0);
    k_gemm5<64, 0><<<dim3(MB, 1), 128, 2 * STAGE_B>>>(xh, img + IMG_EMB, emb_b, hA, hAh, NN, HID, 1);
    k_gemm5<128, 1><<<dim3(MB, 8), 128, 4 * STAGE_B>>>(hAh, img + IMG_WB, bB, nullptr, xlrh, NN, 1024, 0);

    // join: edge kernel needs both xlr (main) and csr (side)
    cudaStreamWaitEvent(0, evJoin, 0);

    // layer 1 edge
    float* hc = hA;   __half* hch = hAh;
    float* hn = hB;   __half* hnh = hBh;
    k_gat_edge<<<(NN + 3) / 4, 256>>>(xlrh, att, cbias, hc, hn, hnh, offs, csr);
    { float* t = hc; hc = hn; hn = t; __half* th = hch; hch = hnh; hnh = th; }

    // layers 2..3
    for (int l = 1; l < LAYERS; l++) {
        k_gemm5<128, 1><<<dim3(MB, 8), 128, 4 * STAGE_B>>>(
            hch, img + IMG_WB + (size_t)l * 65536, bB + (size_t)l * 1024, nullptr, xlrh, NN, 1024, 0);
        k_gat_edge<<<(NN + 3) / 4, 256>>>(xlrh, att + (size_t)l * HEADS * HID,
                                          cbias + l * HID, hc, hn, hnh, offs, csr);
        float* t = hc; hc = hn; hn = t; __half* th = hch; hch = hnh; hnh = th;
    }

    // fused predictor
    k_pred_fused<<<MB, 128, G5_SMEM>>>(hch, img + IMG_P1, img + IMG_P2,
                                       p1_b, p2b, p3_W, p3_b, out, NN);

    cudaEventDestroy(evFork);
    cudaEventDestroy(evH2);
    cudaEventDestroy(evJoin);
    cudaStreamDestroy(s2);
}